// round 6
// baseline (speedup 1.0000x reference)
#include <cuda_runtime.h>
#include <cuda_bf16.h>
#include <cstdint>

#define BB 4
#define CC 256
#define CQ 64
#define NN 4096

// ---------------- scratch (device globals; no allocations) ----------------
__device__ __nv_bfloat16 g_A[(size_t)BB * NN * NN];     // U = exp(E), bf16, unnormalized
__device__ __nv_bfloat16 g_xhi[(size_t)BB * CC * NN];
__device__ __nv_bfloat16 g_xlo[(size_t)BB * CC * NN];
__device__ __nv_bfloat16 g_Qthi[(size_t)BB * NN * CQ];  // Q transposed [n][o]
__device__ __nv_bfloat16 g_Qtlo[(size_t)BB * NN * CQ];
__device__ __nv_bfloat16 g_Khi[(size_t)BB * CQ * NN];
__device__ __nv_bfloat16 g_Klo[(size_t)BB * CQ * NN];
__device__ __nv_bfloat16 g_Wstkhi[640 * CC];            // Wq(64);Wk(64);Wc(256);Wt(256)
__device__ __nv_bfloat16 g_Wstklo[640 * CC];
__device__ float g_W2raw[(size_t)BB * CC * NN];         // (Wc@x + bc)
__device__ float g_Wtx[(size_t)BB * CC * NN];           // Wt@x
__device__ __nv_bfloat16 g_W2hi[(size_t)BB * CC * NN];  // W2raw * invrs[n], split
__device__ __nv_bfloat16 g_W2lo[(size_t)BB * CC * NN];
__device__ float g_T[(size_t)BB * CC * NN];
__device__ float g_invrs[BB * NN];                      // 1 / softmax row sums
__device__ float g_bc[CC];                              // Wt @ bv
__device__ float g_sum[CC];
__device__ float g_sumsq[CC];
__device__ float g_scale[CC];
__device__ float g_shift[CC];

// ---------------- PTX helpers ----------------
__device__ __forceinline__ void mma16816(float* c, const uint32_t* a, const uint32_t* b) {
    asm volatile(
        "mma.sync.aligned.m16n8k16.row.col.f32.bf16.bf16.f32 "
        "{%0,%1,%2,%3}, {%4,%5,%6,%7}, {%8,%9}, {%0,%1,%2,%3};\n"
        : "+f"(c[0]), "+f"(c[1]), "+f"(c[2]), "+f"(c[3])
        : "r"(a[0]), "r"(a[1]), "r"(a[2]), "r"(a[3]), "r"(b[0]), "r"(b[1]));
}
__device__ __forceinline__ void ldsm4(uint32_t* r, uint32_t addr) {
    asm volatile("ldmatrix.sync.aligned.m8n8.x4.shared.b16 {%0,%1,%2,%3}, [%4];"
        : "=r"(r[0]), "=r"(r[1]), "=r"(r[2]), "=r"(r[3]) : "r"(addr));
}
__device__ __forceinline__ void ldsm4t(uint32_t* r, uint32_t addr) {
    asm volatile("ldmatrix.sync.aligned.m8n8.x4.trans.shared.b16 {%0,%1,%2,%3}, [%4];"
        : "=r"(r[0]), "=r"(r[1]), "=r"(r[2]), "=r"(r[3]) : "r"(addr));
}
__device__ __forceinline__ void cpasync16(uint32_t saddr, const void* g) {
    asm volatile("cp.async.cg.shared.global [%0], [%1], 16;" :: "r"(saddr), "l"(g));
}
__device__ __forceinline__ void cp_commit() { asm volatile("cp.async.commit_group;" ::: "memory"); }

__device__ __forceinline__ void split1(float v, __nv_bfloat16& h, __nv_bfloat16& l) {
    h = __float2bfloat16(v);
    l = __float2bfloat16(v - __bfloat162float(h));
}
__device__ __forceinline__ void split_pack(float a, float b, __nv_bfloat162& hi2, __nv_bfloat162& lo2) {
    __nv_bfloat16 ha, la, hb, lb;
    split1(a, ha, la); split1(b, hb, lb);
    hi2.x = ha; hi2.y = hb;
    lo2.x = la; lo2.y = lb;
}

// ---------------- unified bf16-split tensor-core GEMM ----------------
// C[M,N] = (Ahi+Alo)[M,K] @ (B0(+B1))[K,N]     ldb = ldc = NN
// EPI 1 = stacked projection: by0 -> Qt/K splits; by1-2 -> W2raw fp32 (+bc);
//         by3-4 -> Wtx fp32
// EPI 5 = Y gemm: in-loop invrs-weighted colsum from U smem tiles;
//         epilogue t = Wtx + bt - Y/(1e-9+colsum), BN stats, store g_T
#define SA_STRIDE 24
#define SB_STRIDE 136

template<int NB, int EPI>
__global__ __launch_bounds__(256)
void mma_gemm_kernel(const __nv_bfloat16* __restrict__ Ahi, const __nv_bfloat16* __restrict__ Alo,
                     int lda, size_t aBS,
                     const __nv_bfloat16* __restrict__ B0, const __nv_bfloat16* __restrict__ B1,
                     size_t bBS,
                     float* __restrict__ C, size_t cBS, int K,
                     const float* __restrict__ bias,
                     const float* __restrict__ aux, size_t auxBS)
{
    __shared__ __align__(16) __nv_bfloat16 sA[2][2][128 * SA_STRIDE];
    __shared__ __align__(16) __nv_bfloat16 sB[2][NB][16 * SB_STRIDE];
    __shared__ float s_cs[128];

    const int bz = blockIdx.z;
    Ahi += (size_t)bz * aBS;  Alo += (size_t)bz * aBS;
    B0  += (size_t)bz * bBS;
    if (NB == 2) B1 += (size_t)bz * bBS;
    C += (size_t)bz * cBS;
    if (EPI == 5) aux += (size_t)bz * auxBS;

    const int row0 = blockIdx.y * 128;
    const int col0 = blockIdx.x * 128;
    const int tid  = threadIdx.x;
    const int lane = tid & 31, warp = tid >> 5;
    const int wm = warp & 3;
    const int wn = warp >> 2;

    const int ar = tid >> 1, ac = (tid & 1) * 8;
    const int bk = tid >> 4, bc = (tid & 15) * 8;
    const size_t gA = (size_t)(row0 + ar) * lda + ac;
    const size_t gB = (size_t)bk * NN + col0 + bc;

    const uint32_t sAbase = (uint32_t)__cvta_generic_to_shared(&sA[0][0][0]);
    const uint32_t sBbase = (uint32_t)__cvta_generic_to_shared(&sB[0][0][0]);
    const uint32_t sAst = (uint32_t)(ar * SA_STRIDE + ac) * 2;
    const uint32_t sBst = (uint32_t)(bk * SB_STRIDE + bc) * 2;

    constexpr uint32_t A_PLANE = 128 * SA_STRIDE * 2;
    constexpr uint32_t B_PLANE = 16 * SB_STRIDE * 2;
    constexpr uint32_t A_STAGE = 2 * A_PLANE;
    constexpr uint32_t B_STAGE = NB * B_PLANE;

    float acc[2][8][4];
#pragma unroll
    for (int i = 0; i < 2; i++)
#pragma unroll
        for (int j = 0; j < 8; j++)
#pragma unroll
            for (int k = 0; k < 4; k++) acc[i][j][k] = 0.f;

    const int KT = K >> 4;

    auto issue = [&](int kt, int stage) {
        const size_t ka = gA + (size_t)kt * 16;
        const size_t kb = gB + (size_t)kt * 16 * NN;
        const uint32_t aoff = sAbase + stage * A_STAGE + sAst;
        const uint32_t boff = sBbase + stage * B_STAGE + sBst;
        cpasync16(aoff,           Ahi + ka);
        cpasync16(aoff + A_PLANE, Alo + ka);
        cpasync16(boff,           B0 + kb);
        if (NB == 2) cpasync16(boff + B_PLANE, B1 + kb);
    };

    issue(0, 0); cp_commit();

    const int lr = lane & 15, lc8 = (lane >> 4) * 8;
    const uint32_t aAddrBase = sAbase + ((wm * 32 + lr) * SA_STRIDE + lc8) * 2;
    const uint32_t bAddrBase = sBbase + (lr * SB_STRIDE + wn * 64 + lc8) * 2;

    // colsum partial assignment (EPI 5): thread -> (column, k-half)
    const int csm = tid & 127;
    const int csh = tid >> 7;
    float cs_part = 0.f;

    for (int kt = 0; kt < KT; kt++) {
        const int cur = kt & 1;
        if (kt + 1 < KT) {
            issue(kt + 1, cur ^ 1); cp_commit();
            asm volatile("cp.async.wait_group 1;" ::: "memory");
        } else {
            asm volatile("cp.async.wait_group 0;" ::: "memory");
        }
        __syncthreads();

        const uint32_t aS = cur * A_STAGE;
        const uint32_t bS = cur * B_STAGE;

        uint32_t ah[2][4], al[2][4];
#pragma unroll
        for (int mi = 0; mi < 2; mi++) {
            ldsm4(ah[mi], aAddrBase + aS + mi * 16 * SA_STRIDE * 2);
            ldsm4(al[mi], aAddrBase + aS + A_PLANE + mi * 16 * SA_STRIDE * 2);
        }
        uint32_t bh[4][4], bl[4][4];
#pragma unroll
        for (int j = 0; j < 4; j++) {
            ldsm4t(bh[j], bAddrBase + bS + j * 16 * 2);
            if (NB == 2) ldsm4t(bl[j], bAddrBase + bS + B_PLANE + j * 16 * 2);
        }
#pragma unroll
        for (int mi = 0; mi < 2; mi++) {
#pragma unroll
            for (int j = 0; j < 4; j++) {
                mma16816(acc[mi][2 * j],     ah[mi], &bh[j][0]);
                mma16816(acc[mi][2 * j + 1], ah[mi], &bh[j][2]);
                if (NB == 2) {
                    mma16816(acc[mi][2 * j],     ah[mi], &bl[j][0]);
                    mma16816(acc[mi][2 * j + 1], ah[mi], &bl[j][2]);
                }
                mma16816(acc[mi][2 * j],     al[mi], &bh[j][0]);
                mma16816(acc[mi][2 * j + 1], al[mi], &bh[j][2]);
            }
        }

        if (EPI == 5) {
            // weighted colsum from resident U tile: cs[m] += invrs[k] * U[k,m]
            const float* ivp = &g_invrs[bz * NN + kt * 16 + csh * 8];
#pragma unroll
            for (int j = 0; j < 8; j++) {
                const float w = __ldg(&ivp[j]);
                cs_part += w * __bfloat162float(sB[cur][0][(csh * 8 + j) * SB_STRIDE + csm]);
            }
        }
        __syncthreads();
    }

    const int gid = lane >> 2, t4 = lane & 3;

    if (EPI == 1) {
        const int by = blockIdx.y;
#pragma unroll
        for (int mi = 0; mi < 2; mi++)
#pragma unroll
            for (int nj = 0; nj < 8; nj++) {
                const int r = row0 + wm * 32 + mi * 16 + gid;
                const int col = col0 + wn * 64 + nj * 8 + t4 * 2;
                const float v00 = acc[mi][nj][0], v01 = acc[mi][nj][1];
                const float v10 = acc[mi][nj][2], v11 = acc[mi][nj][3];
                if (by == 0) {
                    if (r < 64) {  // Q -> transposed split [n][o]
                        const size_t base = (size_t)bz * NN * CQ;
                        __nv_bfloat16 h, l;
                        split1(v00, h, l); g_Qthi[base + (size_t)col * CQ + r] = h;       g_Qtlo[base + (size_t)col * CQ + r] = l;
                        split1(v01, h, l); g_Qthi[base + (size_t)(col + 1) * CQ + r] = h; g_Qtlo[base + (size_t)(col + 1) * CQ + r] = l;
                        split1(v10, h, l); g_Qthi[base + (size_t)col * CQ + r + 8] = h;       g_Qtlo[base + (size_t)col * CQ + r + 8] = l;
                        split1(v11, h, l); g_Qthi[base + (size_t)(col + 1) * CQ + r + 8] = h; g_Qtlo[base + (size_t)(col + 1) * CQ + r + 8] = l;
                    } else {       // K -> split [o][n]
                        const int kr = r - 64;
                        const size_t base = (size_t)bz * CQ * NN;
                        __nv_bfloat162 h2, l2;
                        split_pack(v00, v01, h2, l2);
                        *(__nv_bfloat162*)&g_Khi[base + (size_t)kr * NN + col] = h2;
                        *(__nv_bfloat162*)&g_Klo[base + (size_t)kr * NN + col] = l2;
                        split_pack(v10, v11, h2, l2);
                        *(__nv_bfloat162*)&g_Khi[base + (size_t)(kr + 8) * NN + col] = h2;
                        *(__nv_bfloat162*)&g_Klo[base + (size_t)(kr + 8) * NN + col] = l2;
                    }
                } else if (by <= 2) {   // W2raw = Wc@x + bc, fp32
                    const int o = r - 128;
                    float* dst = g_W2raw + (size_t)bz * CC * NN;
                    const float b0 = g_bc[o], b1 = g_bc[o + 8];
                    *(float2*)&dst[(size_t)o * NN + col]       = make_float2(v00 + b0, v01 + b0);
                    *(float2*)&dst[(size_t)(o + 8) * NN + col] = make_float2(v10 + b1, v11 + b1);
                } else {                // Wtx fp32
                    const int o = r - 384;
                    float* dst = g_Wtx + (size_t)bz * CC * NN;
                    *(float2*)&dst[(size_t)o * NN + col]       = make_float2(v00, v01);
                    *(float2*)&dst[(size_t)(o + 8) * NN + col] = make_float2(v10, v11);
                }
            }
    }

    if (EPI == 5) {
        // finish colsum: combine halves, invert
        if (csh == 1) s_cs[csm] = cs_part;
        __syncthreads();
        if (csh == 0) s_cs[csm] = 1.0f / (1e-9f + s_cs[csm] + cs_part);
        __syncthreads();

        float ssum[2][2] = {{0.f, 0.f}, {0.f, 0.f}};
        float ssq[2][2]  = {{0.f, 0.f}, {0.f, 0.f}};
#pragma unroll
        for (int mi = 0; mi < 2; mi++)
#pragma unroll
            for (int nj = 0; nj < 8; nj++) {
                const int r = row0 + wm * 32 + mi * 16 + gid;
                const int cl = wn * 64 + nj * 8 + t4 * 2;
                const int col = col0 + cl;
                const float inv0 = s_cs[cl], inv1 = s_cs[cl + 1];
                const float b0 = bias[r], b1 = bias[r + 8];
                const float2 w0 = *(const float2*)&aux[(size_t)r * NN + col];
                const float2 w1 = *(const float2*)&aux[(size_t)(r + 8) * NN + col];
                const float v00 = w0.x + b0 - inv0 * acc[mi][nj][0];
                const float v01 = w0.y + b0 - inv1 * acc[mi][nj][1];
                const float v10 = w1.x + b1 - inv0 * acc[mi][nj][2];
                const float v11 = w1.y + b1 - inv1 * acc[mi][nj][3];
                *(float2*)&C[(size_t)r * NN + col]       = make_float2(v00, v01);
                *(float2*)&C[(size_t)(r + 8) * NN + col] = make_float2(v10, v11);
                ssum[mi][0] += v00 + v01;  ssq[mi][0] += v00 * v00 + v01 * v01;
                ssum[mi][1] += v10 + v11;  ssq[mi][1] += v10 * v10 + v11 * v11;
            }
#pragma unroll
        for (int mi = 0; mi < 2; mi++)
#pragma unroll
            for (int h = 0; h < 2; h++) {
                const int r = row0 + wm * 32 + mi * 16 + gid + h * 8;
                atomicAdd(&g_sum[r], ssum[mi][h]);
                atomicAdd(&g_sumsq[r], ssq[mi][h]);
            }
    }
}

// ---------------- fused energy + exp + rowsum -> U bf16 ----------------
#define QA_ST 72
#define KB_ST 136

__global__ __launch_bounds__(256)
void attn_kernel()
{
    extern __shared__ __align__(16) char dsm[];
    __nv_bfloat16* sQ = (__nv_bfloat16*)dsm;
    __nv_bfloat16* sK = sQ + 2 * 128 * QA_ST;
    float* s_rs = (float*)(sK + 2 * 2 * 64 * KB_ST);

    const int b  = blockIdx.y;
    const int r0 = blockIdx.x * 128;
    const int tid = threadIdx.x;
    const int lane = tid & 31, warp = tid >> 5;
    const int wm = warp & 3, wn = warp >> 2;

    if (tid < 128) s_rs[tid] = 0.f;

    const uint32_t sQb = (uint32_t)__cvta_generic_to_shared(sQ);
    const uint32_t sKb = (uint32_t)__cvta_generic_to_shared(sK);

    const __nv_bfloat16* Qhi = g_Qthi + (size_t)b * NN * CQ;
    const __nv_bfloat16* Qlo = g_Qtlo + (size_t)b * NN * CQ;
#pragma unroll
    for (int p = 0; p < 4; p++) {
        const int idx = p * 256 + tid;
        const int row = idx >> 3, c8 = (idx & 7) * 8;
        cpasync16(sQb + (uint32_t)(row * QA_ST + c8) * 2,
                  Qhi + (size_t)(r0 + row) * CQ + c8);
        cpasync16(sQb + (uint32_t)(128 * QA_ST + row * QA_ST + c8) * 2,
                  Qlo + (size_t)(r0 + row) * CQ + c8);
    }
    cp_commit();

    const __nv_bfloat16* Khi = g_Khi + (size_t)b * CQ * NN;
    const __nv_bfloat16* Klo = g_Klo + (size_t)b * CQ * NN;
    const int kr = tid >> 4, kc8 = (tid & 15) * 8;

    auto issueK = [&](int tile, int stage) {
        const int c0 = tile * 128;
        const uint32_t base = sKb + (uint32_t)stage * (2 * 64 * KB_ST * 2);
#pragma unroll
        for (int c = 0; c < 4; c++) {
            const int r = kr + c * 16;
            cpasync16(base + (uint32_t)(r * KB_ST + kc8) * 2,
                      Khi + (size_t)r * NN + c0 + kc8);
            cpasync16(base + (uint32_t)(64 * KB_ST + r * KB_ST + kc8) * 2,
                      Klo + (size_t)r * NN + c0 + kc8);
        }
        cp_commit();
    };

    issueK(0, 0);

    const int lr = lane & 15, lc8 = (lane >> 4) * 8;
    const uint32_t aBase = sQb + (uint32_t)((wm * 32 + lr) * QA_ST + lc8) * 2;
    const uint32_t bBase = sKb + (uint32_t)(lr * KB_ST + wn * 64 + lc8) * 2;
    constexpr uint32_t QPLANE = 128 * QA_ST * 2;
    constexpr uint32_t KPLANE = 64 * KB_ST * 2;
    constexpr uint32_t KSTAGE = 2 * KPLANE;

    const int gid = lane >> 2, t4 = lane & 3;
    float rowsum[2][2] = {{0.f, 0.f}, {0.f, 0.f}};
    __nv_bfloat16* U = g_A + (size_t)b * NN * NN;

    for (int tile = 0; tile < 32; tile++) {
        const int cur = tile & 1;
        if (tile + 1 < 32) {
            issueK(tile + 1, cur ^ 1);
            asm volatile("cp.async.wait_group 1;" ::: "memory");
        } else {
            asm volatile("cp.async.wait_group 0;" ::: "memory");
        }
        __syncthreads();

        const uint32_t bS = cur * KSTAGE;

        float acc[2][8][4];
#pragma unroll
        for (int i = 0; i < 2; i++)
#pragma unroll
            for (int j = 0; j < 8; j++)
#pragma unroll
                for (int k = 0; k < 4; k++) acc[i][j][k] = 0.f;

#pragma unroll
        for (int ch = 0; ch < 4; ch++) {
            uint32_t ah[2][4], al[2][4];
#pragma unroll
            for (int mi = 0; mi < 2; mi++) {
                ldsm4(ah[mi], aBase + ch * 32 + mi * 16 * QA_ST * 2);
                ldsm4(al[mi], aBase + QPLANE + ch * 32 + mi * 16 * QA_ST * 2);
            }
            uint32_t bh[4][4], bl[4][4];
#pragma unroll
            for (int j = 0; j < 4; j++) {
                ldsm4t(bh[j], bBase + bS + ch * 16 * KB_ST * 2 + j * 16 * 2);
                ldsm4t(bl[j], bBase + bS + KPLANE + ch * 16 * KB_ST * 2 + j * 16 * 2);
            }
#pragma unroll
            for (int mi = 0; mi < 2; mi++)
#pragma unroll
                for (int j = 0; j < 4; j++) {
                    mma16816(acc[mi][2 * j],     ah[mi], &bh[j][0]);
                    mma16816(acc[mi][2 * j + 1], ah[mi], &bh[j][2]);
                    mma16816(acc[mi][2 * j],     ah[mi], &bl[j][0]);
                    mma16816(acc[mi][2 * j + 1], ah[mi], &bl[j][2]);
                    mma16816(acc[mi][2 * j],     al[mi], &bh[j][0]);
                    mma16816(acc[mi][2 * j + 1], al[mi], &bh[j][2]);
                }
        }

        const int c0 = tile * 128;
#pragma unroll
        for (int mi = 0; mi < 2; mi++)
#pragma unroll
            for (int nj = 0; nj < 8; nj++) {
                const int row = r0 + wm * 32 + mi * 16 + gid;
                const int col = c0 + wn * 64 + nj * 8 + t4 * 2;
                const float e00 = __expf(acc[mi][nj][0]);
                const float e01 = __expf(acc[mi][nj][1]);
                const float e10 = __expf(acc[mi][nj][2]);
                const float e11 = __expf(acc[mi][nj][3]);
                rowsum[mi][0] += e00 + e01;
                rowsum[mi][1] += e10 + e11;
                __nv_bfloat162 p0, p1;
                p0.x = __float2bfloat16(e00); p0.y = __float2bfloat16(e01);
                p1.x = __float2bfloat16(e10); p1.y = __float2bfloat16(e11);
                *(__nv_bfloat162*)&U[(size_t)row * NN + col] = p0;
                *(__nv_bfloat162*)&U[(size_t)(row + 8) * NN + col] = p1;
            }
        __syncthreads();
    }

#pragma unroll
    for (int mi = 0; mi < 2; mi++)
#pragma unroll
        for (int h = 0; h < 2; h++) {
            float v = rowsum[mi][h];
            v += __shfl_xor_sync(0xffffffffu, v, 1);
            v += __shfl_xor_sync(0xffffffffu, v, 2);
            if (t4 == 0) atomicAdd(&s_rs[wm * 32 + mi * 16 + gid + h * 8], v);
        }
    __syncthreads();
    if (tid < 128) g_invrs[b * NN + r0 + tid] = 1.0f / s_rs[tid];
}

// ---------------- W2' = W2raw * invrs[n], split to bf16 hi/lo ----------------
__global__ void w2scale_kernel()
{
    const int b = blockIdx.z;
    const size_t i4 = (size_t)blockIdx.x * 256 + threadIdx.x;
    float4 v = ((const float4*)(g_W2raw + (size_t)b * CC * NN))[i4];
    const int n4 = (int)((i4 * 4) & (NN - 1));
    const float4 w = *(const float4*)&g_invrs[b * NN + n4];
    v.x *= w.x; v.y *= w.y; v.z *= w.z; v.w *= w.w;
    __nv_bfloat162 ha, la, hb, lb;
    split_pack(v.x, v.y, ha, la);
    split_pack(v.z, v.w, hb, lb);
    uint2 hv, lv;
    hv.x = *(uint32_t*)&ha; hv.y = *(uint32_t*)&hb;
    lv.x = *(uint32_t*)&la; lv.y = *(uint32_t*)&lb;
    ((uint2*)(g_W2hi + (size_t)b * CC * NN))[i4] = hv;
    ((uint2*)(g_W2lo + (size_t)b * CC * NN))[i4] = lv;
}

// ---------------- weight prep ----------------
// Wc = Wt @ Wv, split into g_Wstk rows 128..383
__global__ void wc_kernel(const float* __restrict__ Wt, const float* __restrict__ Wv)
{
    __shared__ float a[16][17], bsh[16][17];
    const int tx = threadIdx.x, ty = threadIdx.y;
    const int o0 = blockIdx.y * 16, c0 = blockIdx.x * 16;
    float acc = 0.f;
    for (int kb = 0; kb < 16; kb++) {
        a[ty][tx]   = Wt[(o0 + ty) * CC + kb * 16 + tx];
        bsh[ty][tx] = Wv[(kb * 16 + ty) * CC + c0 + tx];
        __syncthreads();
#pragma unroll
        for (int kk = 0; kk < 16; kk++) acc += a[ty][kk] * bsh[kk][tx];
        __syncthreads();
    }
    __nv_bfloat16 h, l;
    split1(acc, h, l);
    const int idx = (128 + o0 + ty) * CC + c0 + tx;
    g_Wstkhi[idx] = h; g_Wstklo[idx] = l;
}

// bc = Wt @ bv; also zero BN accumulators
__global__ void bc_zero_kernel(const float* __restrict__ Wt, const float* __restrict__ bv)
{
    const int o = threadIdx.x;
    float s = 0.f;
    for (int k = 0; k < CC; k++) s += Wt[o * CC + k] * bv[k];
    g_bc[o] = s;
    g_sum[o] = 0.f;
    g_sumsq[o] = 0.f;
}

// rows 0..127 (Wq;Wk) and 384..639 (Wt) of the weight stack
__global__ void wstk_split_kernel(const float* __restrict__ Wq, const float* __restrict__ Wk,
                                  const float* __restrict__ Wt)
{
    const int t = blockIdx.x * 256 + threadIdx.x;   // 0 .. 384*CC-1
    float v; int dst;
    if (t < 64 * CC)       { v = Wq[t];            dst = t; }
    else if (t < 128 * CC) { v = Wk[t - 64 * CC];  dst = t; }
    else                   { v = Wt[t - 128 * CC]; dst = 256 * CC + t; }  // 384*CC + (t-128*CC)
    __nv_bfloat16 h, l;
    split1(v, h, l);
    g_Wstkhi[dst] = h; g_Wstklo[dst] = l;
}

// ---------------- x split ----------------
__global__ void split4_kernel(const float* __restrict__ src, size_t srcBS,
                              __nv_bfloat16* __restrict__ hi, __nv_bfloat16* __restrict__ lo,
                              size_t dstBS)
{
    const size_t i4 = (size_t)blockIdx.x * 256 + threadIdx.x;
    const float4 v = ((const float4*)(src + (size_t)blockIdx.z * srcBS))[i4];
    __nv_bfloat162 ha, la, hb, lb;
    split_pack(v.x, v.y, ha, la);
    split_pack(v.z, v.w, hb, lb);
    uint2 hv, lv;
    hv.x = *(uint32_t*)&ha; hv.y = *(uint32_t*)&hb;
    lv.x = *(uint32_t*)&la; lv.y = *(uint32_t*)&lb;
    ((uint2*)(hi + (size_t)blockIdx.z * dstBS))[i4] = hv;
    ((uint2*)(lo + (size_t)blockIdx.z * dstBS))[i4] = lv;
}

// ---------------- BN finalize + output ----------------
__global__ void bn_finalize_kernel(const float* __restrict__ gamma, const float* __restrict__ beta)
{
    const int c = threadIdx.x;
    const float cnt = (float)(BB * NN);
    const float mean = g_sum[c] / cnt;
    const float var = g_sumsq[c] / cnt - mean * mean;
    const float sc = gamma[c] * rsqrtf(var + 1e-5f);
    g_scale[c] = sc;
    g_shift[c] = beta[c] - mean * sc;
}

__global__ void final_kernel(const float* __restrict__ x, float* __restrict__ out)
{
    const size_t idx = (size_t)blockIdx.x * 256 + threadIdx.x;
    const int c = (int)((idx >> 12) & (CC - 1));
    const float t = g_T[idx] * g_scale[c] + g_shift[c];
    out[idx] = x[idx] + fmaxf(t, 0.f);
}

// ---------------- launch ----------------
extern "C" void kernel_launch(void* const* d_in, const int* in_sizes, int n_in,
                              void* d_out, int out_size)
{
    const float* x     = (const float*)d_in[0];
    const float* Wq    = (const float*)d_in[1];
    const float* Wk    = (const float*)d_in[2];
    const float* Wv    = (const float*)d_in[3];
    const float* bv    = (const float*)d_in[4];
    const float* Wt    = (const float*)d_in[5];
    const float* bt    = (const float*)d_in[6];
    const float* gamma = (const float*)d_in[7];
    const float* beta  = (const float*)d_in[8];
    float* out = (float*)d_out;

    float *pT, *pWtx;
    __nv_bfloat16 *pA, *pXhi, *pXlo, *pW2hi, *pW2lo, *pWstkhi, *pWstklo;
    cudaGetSymbolAddress((void**)&pT, g_T);
    cudaGetSymbolAddress((void**)&pWtx, g_Wtx);
    cudaGetSymbolAddress((void**)&pA, g_A);
    cudaGetSymbolAddress((void**)&pXhi, g_xhi);
    cudaGetSymbolAddress((void**)&pXlo, g_xlo);
    cudaGetSymbolAddress((void**)&pW2hi, g_W2hi);
    cudaGetSymbolAddress((void**)&pW2lo, g_W2lo);
    cudaGetSymbolAddress((void**)&pWstkhi, g_Wstkhi);
    cudaGetSymbolAddress((void**)&pWstklo, g_Wstklo);

    const int attn_smem = (2 * 128 * QA_ST + 2 * 2 * 64 * KB_ST) * 2 + 128 * 4;
    cudaFuncSetAttribute(attn_kernel, cudaFuncAttributeMaxDynamicSharedMemorySize, attn_smem);

    // weight prep
    bc_zero_kernel<<<1, CC>>>(Wt, bv);
    wc_kernel<<<dim3(16, 16), dim3(16, 16)>>>(Wt, Wv);
    wstk_split_kernel<<<384 * CC / 256, 256>>>(Wq, Wk, Wt);
    split4_kernel<<<dim3(CC * NN / 1024, 1, BB), 256>>>(x, (size_t)CC * NN, pXhi, pXlo, (size_t)CC * NN);

    // stacked projection: [640,256] @ [256,4096]
    // by0 -> Qt/K splits; by1-2 -> W2raw (+bc); by3-4 -> Wtx
    mma_gemm_kernel<2, 1><<<dim3(NN / 128, 5, BB), 256>>>(
        pWstkhi, pWstklo, CC, 0,
        pXhi, pXlo, (size_t)CC * NN,
        pT /*unused*/, 0, CC, nullptr, nullptr, 0);

    // fused energy + exp + rowsum -> U (bf16), invrs
    attn_kernel<<<dim3(NN / 128, BB), 256, attn_smem>>>();

    // W2' = W2raw * invrs, split
    w2scale_kernel<<<dim3(CC * NN / 1024, 1, BB), 256>>>();

    // Y = W2' @ U with in-loop colsum; epilogue t = Wtx + bt - Y/(1e-9+cs), BN stats
    mma_gemm_kernel<1, 5><<<dim3(NN / 128, CC / 128, BB), 256>>>(
        pW2hi, pW2lo, NN, (size_t)CC * NN,
        pA, nullptr, (size_t)NN * NN,
        pT, (size_t)CC * NN, NN, bt, pWtx, (size_t)CC * NN);

    bn_finalize_kernel<<<1, CC>>>(gamma, beta);

    final_kernel<<<(size_t)BB * CC * NN / 256, 256>>>(x, out);
}

// round 8
// speedup vs baseline: 1.3113x; 1.3113x over previous
#include <cuda_runtime.h>
#include <cuda_bf16.h>
#include <cstdint>

#define BB 4
#define CC 256
#define CQ 64
#define NN 4096

// ---------------- scratch (device globals; no allocations) ----------------
__device__ __nv_bfloat16 g_A[(size_t)BB * NN * NN];     // U = exp(E), bf16, unnormalized
__device__ __nv_bfloat16 g_xhi[(size_t)BB * CC * NN];
__device__ __nv_bfloat16 g_xlo[(size_t)BB * CC * NN];
__device__ __nv_bfloat16 g_Vhi[(size_t)BB * CC * NN];
__device__ __nv_bfloat16 g_Vlo[(size_t)BB * CC * NN];
__device__ __nv_bfloat16 g_dhi[(size_t)BB * CC * NN];   // d = x - xr*colscale, split
__device__ __nv_bfloat16 g_dlo[(size_t)BB * CC * NN];
__device__ __nv_bfloat16 g_Qthi[(size_t)BB * NN * CQ];  // Q transposed [n][o]
__device__ __nv_bfloat16 g_Qtlo[(size_t)BB * NN * CQ];
__device__ __nv_bfloat16 g_Khi[(size_t)BB * CQ * NN];
__device__ __nv_bfloat16 g_Klo[(size_t)BB * CQ * NN];
__device__ __nv_bfloat16 g_Wqkvhi[384 * CC];            // Wq(64) ; Wk(64) ; Wv(256) rows
__device__ __nv_bfloat16 g_Wqkvlo[384 * CC];
__device__ __nv_bfloat16 g_Wthi[CC * CC];
__device__ __nv_bfloat16 g_Wtlo[CC * CC];
__device__ float g_T[(size_t)BB * CC * NN];
__device__ float g_invrs[BB * NN];                      // 1 / softmax row sums
__device__ float g_colsum[BB * NN];
__device__ float g_sum[CC];
__device__ float g_sumsq[CC];
__device__ float g_scale[CC];
__device__ float g_shift[CC];

// ---------------- PTX helpers ----------------
__device__ __forceinline__ void mma16816(float* c, const uint32_t* a, const uint32_t* b) {
    asm volatile(
        "mma.sync.aligned.m16n8k16.row.col.f32.bf16.bf16.f32 "
        "{%0,%1,%2,%3}, {%4,%5,%6,%7}, {%8,%9}, {%0,%1,%2,%3};\n"
        : "+f"(c[0]), "+f"(c[1]), "+f"(c[2]), "+f"(c[3])
        : "r"(a[0]), "r"(a[1]), "r"(a[2]), "r"(a[3]), "r"(b[0]), "r"(b[1]));
}
__device__ __forceinline__ void ldsm4(uint32_t* r, uint32_t addr) {
    asm volatile("ldmatrix.sync.aligned.m8n8.x4.shared.b16 {%0,%1,%2,%3}, [%4];"
        : "=r"(r[0]), "=r"(r[1]), "=r"(r[2]), "=r"(r[3]) : "r"(addr));
}
__device__ __forceinline__ void ldsm4t(uint32_t* r, uint32_t addr) {
    asm volatile("ldmatrix.sync.aligned.m8n8.x4.trans.shared.b16 {%0,%1,%2,%3}, [%4];"
        : "=r"(r[0]), "=r"(r[1]), "=r"(r[2]), "=r"(r[3]) : "r"(addr));
}
__device__ __forceinline__ void cpasync16(uint32_t saddr, const void* g) {
    asm volatile("cp.async.cg.shared.global [%0], [%1], 16;" :: "r"(saddr), "l"(g));
}
__device__ __forceinline__ void cp_commit() { asm volatile("cp.async.commit_group;" ::: "memory"); }

__device__ __forceinline__ void split1(float v, __nv_bfloat16& h, __nv_bfloat16& l) {
    h = __float2bfloat16(v);
    l = __float2bfloat16(v - __bfloat162float(h));
}
__device__ __forceinline__ void split_pack(float a, float b, __nv_bfloat162& hi2, __nv_bfloat162& lo2) {
    __nv_bfloat16 ha, la, hb, lb;
    split1(a, ha, la); split1(b, hb, lb);
    hi2.x = ha; hi2.y = hb;
    lo2.x = la; lo2.y = lb;
}

// ---------------- unified bf16-split tensor-core GEMM, 4-stage pipeline ----------------
// C[M,N] = (Ahi+Alo)[M,K] @ (B0(+B1))[K,N]     ldb = ldc = NN
// EPI 1 = stacked QKV projection epilogue
// EPI 2 = transform (+bias, BN stats)
// EPI 3 = xr->d: d = aux(x) - acc/(1e-9+colsum[col]), split store
#define SA_STRIDE 24
#define SB_STRIDE 136

template<int NB, int EPI>
__global__ __launch_bounds__(256)
void mma_gemm_kernel(const __nv_bfloat16* __restrict__ Ahi, const __nv_bfloat16* __restrict__ Alo,
                     int lda, size_t aBS,
                     const __nv_bfloat16* __restrict__ B0, const __nv_bfloat16* __restrict__ B1,
                     size_t bBS,
                     float* __restrict__ C, size_t cBS, int K,
                     const float* __restrict__ bias,
                     const float* __restrict__ aux, size_t auxBS)
{
    extern __shared__ __align__(16) char dynsm[];
    constexpr uint32_t A_PLANE = 128 * SA_STRIDE * 2;          // 6144
    constexpr uint32_t B_PLANE = 16 * SB_STRIDE * 2;           // 4352
    constexpr uint32_t STAGE   = 2 * A_PLANE + NB * B_PLANE;

    const int bz = blockIdx.z;
    Ahi += (size_t)bz * aBS;  Alo += (size_t)bz * aBS;
    B0  += (size_t)bz * bBS;
    if (NB == 2) B1 += (size_t)bz * bBS;
    C += (size_t)bz * cBS;
    if (EPI == 3) aux += (size_t)bz * auxBS;

    const int row0 = blockIdx.y * 128;
    const int col0 = blockIdx.x * 128;
    const int tid  = threadIdx.x;
    const int lane = tid & 31, warp = tid >> 5;
    const int wm = warp & 3;
    const int wn = warp >> 2;

    const int ar = tid >> 1, ac = (tid & 1) * 8;
    const int bk = tid >> 4, bc = (tid & 15) * 8;
    const size_t gA = (size_t)(row0 + ar) * lda + ac;
    const size_t gB = (size_t)bk * NN + col0 + bc;

    const uint32_t sbase = (uint32_t)__cvta_generic_to_shared(dynsm);
    const uint32_t sAst = (uint32_t)(ar * SA_STRIDE + ac) * 2;
    const uint32_t sBst = 2 * A_PLANE + (uint32_t)(bk * SB_STRIDE + bc) * 2;

    float acc[2][8][4];
#pragma unroll
    for (int i = 0; i < 2; i++)
#pragma unroll
        for (int j = 0; j < 8; j++)
#pragma unroll
            for (int k = 0; k < 4; k++) acc[i][j][k] = 0.f;

    const int KT = K >> 4;

    auto issue = [&](int kt, int s) {
        const size_t ka = gA + (size_t)kt * 16;
        const size_t kb = gB + (size_t)kt * 16 * NN;
        const uint32_t st = sbase + (uint32_t)s * STAGE;
        cpasync16(st + sAst,           Ahi + ka);
        cpasync16(st + A_PLANE + sAst, Alo + ka);
        cpasync16(st + sBst,           B0 + kb);
        if (NB == 2) cpasync16(st + B_PLANE + sBst, B1 + kb);
    };

    // prologue: 3 tiles in flight
#pragma unroll
    for (int s = 0; s < 3; s++) { issue(s, s); cp_commit(); }

    const int lr = lane & 15, lc8 = (lane >> 4) * 8;
    const uint32_t aOff = ((wm * 32 + lr) * SA_STRIDE + lc8) * 2;
    const uint32_t bOff = 2 * A_PLANE + (lr * SB_STRIDE + wn * 64 + lc8) * 2;

    for (int kt = 0; kt < KT; kt++) {
        asm volatile("cp.async.wait_group 2;" ::: "memory");
        __syncthreads();
        // keep group accounting exact with empty commits at the tail
        if (kt + 3 < KT) issue(kt + 3, (kt + 3) & 3);
        cp_commit();

        const uint32_t st = sbase + (uint32_t)(kt & 3) * STAGE;

        uint32_t ah[2][4], al[2][4];
#pragma unroll
        for (int mi = 0; mi < 2; mi++) {
            ldsm4(ah[mi], st + aOff + mi * 16 * SA_STRIDE * 2);
            ldsm4(al[mi], st + A_PLANE + aOff + mi * 16 * SA_STRIDE * 2);
        }
        uint32_t bh[4][4], bl[4][4];
#pragma unroll
        for (int j = 0; j < 4; j++) {
            ldsm4t(bh[j], st + bOff + j * 16 * 2);
            if (NB == 2) ldsm4t(bl[j], st + bOff + B_PLANE + j * 16 * 2);
        }
#pragma unroll
        for (int mi = 0; mi < 2; mi++) {
#pragma unroll
            for (int j = 0; j < 4; j++) {
                mma16816(acc[mi][2 * j],     ah[mi], &bh[j][0]);
                mma16816(acc[mi][2 * j + 1], ah[mi], &bh[j][2]);
                if (NB == 2) {
                    mma16816(acc[mi][2 * j],     ah[mi], &bl[j][0]);
                    mma16816(acc[mi][2 * j + 1], ah[mi], &bl[j][2]);
                }
                mma16816(acc[mi][2 * j],     al[mi], &bh[j][0]);
                mma16816(acc[mi][2 * j + 1], al[mi], &bh[j][2]);
            }
        }
        // no trailing sync: top-of-loop barrier protects buffer reuse
    }

    const int gid = lane >> 2, t4 = lane & 3;

    if (EPI == 1) {
        const int by = blockIdx.y;
#pragma unroll
        for (int mi = 0; mi < 2; mi++)
#pragma unroll
            for (int nj = 0; nj < 8; nj++) {
                const int r = row0 + wm * 32 + mi * 16 + gid;
                const int col = col0 + wn * 64 + nj * 8 + t4 * 2;
                const float v00 = acc[mi][nj][0], v01 = acc[mi][nj][1];
                const float v10 = acc[mi][nj][2], v11 = acc[mi][nj][3];
                if (by == 0) {
                    if (r < 64) {  // Q -> transposed split [n][o]
                        const size_t base = (size_t)bz * NN * CQ;
                        __nv_bfloat16 h, l;
                        split1(v00, h, l); g_Qthi[base + (size_t)col * CQ + r] = h;       g_Qtlo[base + (size_t)col * CQ + r] = l;
                        split1(v01, h, l); g_Qthi[base + (size_t)(col + 1) * CQ + r] = h; g_Qtlo[base + (size_t)(col + 1) * CQ + r] = l;
                        split1(v10, h, l); g_Qthi[base + (size_t)col * CQ + r + 8] = h;       g_Qtlo[base + (size_t)col * CQ + r + 8] = l;
                        split1(v11, h, l); g_Qthi[base + (size_t)(col + 1) * CQ + r + 8] = h; g_Qtlo[base + (size_t)(col + 1) * CQ + r + 8] = l;
                    } else {       // K -> split [o][n]
                        const int kr = r - 64;
                        const size_t base = (size_t)bz * CQ * NN;
                        __nv_bfloat162 h2, l2;
                        split_pack(v00, v01, h2, l2);
                        *(__nv_bfloat162*)&g_Khi[base + (size_t)kr * NN + col] = h2;
                        *(__nv_bfloat162*)&g_Klo[base + (size_t)kr * NN + col] = l2;
                        split_pack(v10, v11, h2, l2);
                        *(__nv_bfloat162*)&g_Khi[base + (size_t)(kr + 8) * NN + col] = h2;
                        *(__nv_bfloat162*)&g_Klo[base + (size_t)(kr + 8) * NN + col] = l2;
                    }
                } else {           // V rows (+bias)
                    const int vr = r - 128;
                    const size_t base = (size_t)bz * CC * NN;
                    const float b0 = bias[vr], b1 = bias[vr + 8];
                    __nv_bfloat162 h2, l2;
                    split_pack(v00 + b0, v01 + b0, h2, l2);
                    *(__nv_bfloat162*)&g_Vhi[base + (size_t)vr * NN + col] = h2;
                    *(__nv_bfloat162*)&g_Vlo[base + (size_t)vr * NN + col] = l2;
                    split_pack(v10 + b1, v11 + b1, h2, l2);
                    *(__nv_bfloat162*)&g_Vhi[base + (size_t)(vr + 8) * NN + col] = h2;
                    *(__nv_bfloat162*)&g_Vlo[base + (size_t)(vr + 8) * NN + col] = l2;
                }
            }
    }

    if (EPI == 2) {
        float ssum[2][2] = {{0.f, 0.f}, {0.f, 0.f}};
        float ssq[2][2]  = {{0.f, 0.f}, {0.f, 0.f}};
#pragma unroll
        for (int mi = 0; mi < 2; mi++)
#pragma unroll
            for (int nj = 0; nj < 8; nj++) {
                const int r = row0 + wm * 32 + mi * 16 + gid;
                const int col = col0 + wn * 64 + nj * 8 + t4 * 2;
                const float b0 = bias[r], b1 = bias[r + 8];
                const float v00 = acc[mi][nj][0] + b0, v01 = acc[mi][nj][1] + b0;
                const float v10 = acc[mi][nj][2] + b1, v11 = acc[mi][nj][3] + b1;
                *(float2*)&C[(size_t)r * NN + col]       = make_float2(v00, v01);
                *(float2*)&C[(size_t)(r + 8) * NN + col] = make_float2(v10, v11);
                ssum[mi][0] += v00 + v01;  ssq[mi][0] += v00 * v00 + v01 * v01;
                ssum[mi][1] += v10 + v11;  ssq[mi][1] += v10 * v10 + v11 * v11;
            }
#pragma unroll
        for (int mi = 0; mi < 2; mi++)
#pragma unroll
            for (int h = 0; h < 2; h++) {
                const int r = row0 + wm * 32 + mi * 16 + gid + h * 8;
                atomicAdd(&g_sum[r], ssum[mi][h]);
                atomicAdd(&g_sumsq[r], ssq[mi][h]);
            }
    }

    if (EPI == 3) {
#pragma unroll
        for (int mi = 0; mi < 2; mi++)
#pragma unroll
            for (int nj = 0; nj < 8; nj++) {
                const int r = row0 + wm * 32 + mi * 16 + gid;
                const int col = col0 + wn * 64 + nj * 8 + t4 * 2;
                const float cs0 = 1.0f / (1e-9f + g_colsum[bz * NN + col]);
                const float cs1 = 1.0f / (1e-9f + g_colsum[bz * NN + col + 1]);
                const size_t base = (size_t)bz * CC * NN;
                const float d00 = aux[(size_t)r * NN + col]       - acc[mi][nj][0] * cs0;
                const float d01 = aux[(size_t)r * NN + col + 1]   - acc[mi][nj][1] * cs1;
                const float d10 = aux[(size_t)(r + 8) * NN + col]     - acc[mi][nj][2] * cs0;
                const float d11 = aux[(size_t)(r + 8) * NN + col + 1] - acc[mi][nj][3] * cs1;
                __nv_bfloat162 h2, l2;
                split_pack(d00, d01, h2, l2);
                *(__nv_bfloat162*)&g_dhi[base + (size_t)r * NN + col] = h2;
                *(__nv_bfloat162*)&g_dlo[base + (size_t)r * NN + col] = l2;
                split_pack(d10, d11, h2, l2);
                *(__nv_bfloat162*)&g_dhi[base + (size_t)(r + 8) * NN + col] = h2;
                *(__nv_bfloat162*)&g_dlo[base + (size_t)(r + 8) * NN + col] = l2;
            }
    }
}

// ---------------- fused energy + exp + rowsum -> U bf16 ----------------
#define QA_ST 72
#define KB_ST 136

__global__ __launch_bounds__(256)
void attn_kernel()
{
    extern __shared__ __align__(16) char dsm[];
    __nv_bfloat16* sQ = (__nv_bfloat16*)dsm;
    __nv_bfloat16* sK = sQ + 2 * 128 * QA_ST;
    float* s_rs = (float*)(sK + 2 * 2 * 64 * KB_ST);

    const int b  = blockIdx.y;
    const int r0 = blockIdx.x * 128;
    const int tid = threadIdx.x;
    const int lane = tid & 31, warp = tid >> 5;
    const int wm = warp & 3, wn = warp >> 2;

    if (tid < 128) s_rs[tid] = 0.f;

    const uint32_t sQb = (uint32_t)__cvta_generic_to_shared(sQ);
    const uint32_t sKb = (uint32_t)__cvta_generic_to_shared(sK);

    const __nv_bfloat16* Qhi = g_Qthi + (size_t)b * NN * CQ;
    const __nv_bfloat16* Qlo = g_Qtlo + (size_t)b * NN * CQ;
#pragma unroll
    for (int p = 0; p < 4; p++) {
        const int idx = p * 256 + tid;
        const int row = idx >> 3, c8 = (idx & 7) * 8;
        cpasync16(sQb + (uint32_t)(row * QA_ST + c8) * 2,
                  Qhi + (size_t)(r0 + row) * CQ + c8);
        cpasync16(sQb + (uint32_t)(128 * QA_ST + row * QA_ST + c8) * 2,
                  Qlo + (size_t)(r0 + row) * CQ + c8);
    }
    cp_commit();

    const __nv_bfloat16* Khi = g_Khi + (size_t)b * CQ * NN;
    const __nv_bfloat16* Klo = g_Klo + (size_t)b * CQ * NN;
    const int kr = tid >> 4, kc8 = (tid & 15) * 8;

    auto issueK = [&](int tile, int stage) {
        const int c0 = tile * 128;
        const uint32_t base = sKb + (uint32_t)stage * (2 * 64 * KB_ST * 2);
#pragma unroll
        for (int c = 0; c < 4; c++) {
            const int r = kr + c * 16;
            cpasync16(base + (uint32_t)(r * KB_ST + kc8) * 2,
                      Khi + (size_t)r * NN + c0 + kc8);
            cpasync16(base + (uint32_t)(64 * KB_ST + r * KB_ST + kc8) * 2,
                      Klo + (size_t)r * NN + c0 + kc8);
        }
        cp_commit();
    };

    issueK(0, 0);

    const int lr = lane & 15, lc8 = (lane >> 4) * 8;
    const uint32_t aBase = sQb + (uint32_t)((wm * 32 + lr) * QA_ST + lc8) * 2;
    const uint32_t bBase = sKb + (uint32_t)(lr * KB_ST + wn * 64 + lc8) * 2;
    constexpr uint32_t QPLANE = 128 * QA_ST * 2;
    constexpr uint32_t KPLANE = 64 * KB_ST * 2;
    constexpr uint32_t KSTAGE = 2 * KPLANE;

    const int gid = lane >> 2, t4 = lane & 3;
    float rowsum[2][2] = {{0.f, 0.f}, {0.f, 0.f}};
    __nv_bfloat16* U = g_A + (size_t)b * NN * NN;

    for (int tile = 0; tile < 32; tile++) {
        const int cur = tile & 1;
        if (tile + 1 < 32) {
            issueK(tile + 1, cur ^ 1);
            asm volatile("cp.async.wait_group 1;" ::: "memory");
        } else {
            asm volatile("cp.async.wait_group 0;" ::: "memory");
        }
        __syncthreads();

        const uint32_t bS = cur * KSTAGE;

        float acc[2][8][4];
#pragma unroll
        for (int i = 0; i < 2; i++)
#pragma unroll
            for (int j = 0; j < 8; j++)
#pragma unroll
                for (int k = 0; k < 4; k++) acc[i][j][k] = 0.f;

#pragma unroll
        for (int ch = 0; ch < 4; ch++) {
            uint32_t ah[2][4], al[2][4];
#pragma unroll
            for (int mi = 0; mi < 2; mi++) {
                ldsm4(ah[mi], aBase + ch * 32 + mi * 16 * QA_ST * 2);
                ldsm4(al[mi], aBase + QPLANE + ch * 32 + mi * 16 * QA_ST * 2);
            }
            uint32_t bh[4][4], bl[4][4];
#pragma unroll
            for (int j = 0; j < 4; j++) {
                ldsm4t(bh[j], bBase + bS + ch * 16 * KB_ST * 2 + j * 16 * 2);
                ldsm4t(bl[j], bBase + bS + KPLANE + ch * 16 * KB_ST * 2 + j * 16 * 2);
            }
#pragma unroll
            for (int mi = 0; mi < 2; mi++)
#pragma unroll
                for (int j = 0; j < 4; j++) {
                    mma16816(acc[mi][2 * j],     ah[mi], &bh[j][0]);
                    mma16816(acc[mi][2 * j + 1], ah[mi], &bh[j][2]);
                    mma16816(acc[mi][2 * j],     ah[mi], &bl[j][0]);
                    mma16816(acc[mi][2 * j + 1], ah[mi], &bl[j][2]);
                    mma16816(acc[mi][2 * j],     al[mi], &bh[j][0]);
                    mma16816(acc[mi][2 * j + 1], al[mi], &bh[j][2]);
                }
        }

        const int c0 = tile * 128;
#pragma unroll
        for (int mi = 0; mi < 2; mi++)
#pragma unroll
            for (int nj = 0; nj < 8; nj++) {
                const int row = r0 + wm * 32 + mi * 16 + gid;
                const int col = c0 + wn * 64 + nj * 8 + t4 * 2;
                const float e00 = __expf(acc[mi][nj][0]);
                const float e01 = __expf(acc[mi][nj][1]);
                const float e10 = __expf(acc[mi][nj][2]);
                const float e11 = __expf(acc[mi][nj][3]);
                rowsum[mi][0] += e00 + e01;
                rowsum[mi][1] += e10 + e11;
                __nv_bfloat162 p0, p1;
                p0.x = __float2bfloat16(e00); p0.y = __float2bfloat16(e01);
                p1.x = __float2bfloat16(e10); p1.y = __float2bfloat16(e11);
                *(__nv_bfloat162*)&U[(size_t)row * NN + col] = p0;
                *(__nv_bfloat162*)&U[(size_t)(row + 8) * NN + col] = p1;
            }
        __syncthreads();
    }

#pragma unroll
    for (int mi = 0; mi < 2; mi++)
#pragma unroll
        for (int h = 0; h < 2; h++) {
            float v = rowsum[mi][h];
            v += __shfl_xor_sync(0xffffffffu, v, 1);
            v += __shfl_xor_sync(0xffffffffu, v, 2);
            if (t4 == 0) atomicAdd(&s_rs[wm * 32 + mi * 16 + gid + h * 8], v);
        }
    __syncthreads();
    if (tid < 128) g_invrs[b * NN + r0 + tid] = 1.0f / s_rs[tid];
}

// ---------------- V in-place rescale: V' = V * invrs[n] ----------------
__global__ void vrescale_kernel()
{
    const int b = blockIdx.z;
    const int idx = blockIdx.x * 256 + threadIdx.x;
    const int m2 = idx & (NN / 2 - 1);
    const size_t o = (size_t)b * CC * (NN / 2) + idx;
    __nv_bfloat162* H = (__nv_bfloat162*)g_Vhi;
    __nv_bfloat162* L = (__nv_bfloat162*)g_Vlo;
    const __nv_bfloat162 h2 = H[o], l2 = L[o];
    const float w0 = g_invrs[b * NN + 2 * m2];
    const float w1 = g_invrs[b * NN + 2 * m2 + 1];
    const float v0 = (__bfloat162float(h2.x) + __bfloat162float(l2.x)) * w0;
    const float v1 = (__bfloat162float(h2.y) + __bfloat162float(l2.y)) * w1;
    __nv_bfloat162 nh, nl;
    split_pack(v0, v1, nh, nl);
    H[o] = nh; L[o] = nl;
}

// ---------------- weighted column sums ----------------
__global__ void colsum_kernel()
{
    const int m2 = blockIdx.x * 256 + threadIdx.x;
    const int b = blockIdx.z;
    const int n0 = blockIdx.y * 128;
    const __nv_bfloat162* A2 = (const __nv_bfloat162*)(g_A + (size_t)b * NN * NN);
    float s0 = 0.f, s1 = 0.f;
#pragma unroll 4
    for (int n = 0; n < 128; n++) {
        const float w = g_invrs[b * NN + n0 + n];
        const __nv_bfloat162 a = A2[(size_t)(n0 + n) * (NN / 2) + m2];
        s0 += __bfloat162float(a.x) * w;
        s1 += __bfloat162float(a.y) * w;
    }
    atomicAdd(&g_colsum[b * NN + 2 * m2 + 0], s0);
    atomicAdd(&g_colsum[b * NN + 2 * m2 + 1], s1);
}

// ---------------- splits ----------------
__global__ void split4_kernel(const float* __restrict__ src, size_t srcBS,
                              __nv_bfloat16* __restrict__ hi, __nv_bfloat16* __restrict__ lo,
                              size_t dstBS)
{
    const size_t i4 = (size_t)blockIdx.x * 256 + threadIdx.x;
    const float4 v = ((const float4*)(src + (size_t)blockIdx.z * srcBS))[i4];
    __nv_bfloat162 ha, la, hb, lb;
    split_pack(v.x, v.y, ha, la);
    split_pack(v.z, v.w, hb, lb);
    uint2 hv, lv;
    hv.x = *(uint32_t*)&ha; hv.y = *(uint32_t*)&hb;
    lv.x = *(uint32_t*)&la; lv.y = *(uint32_t*)&lb;
    ((uint2*)(hi + (size_t)blockIdx.z * dstBS))[i4] = hv;
    ((uint2*)(lo + (size_t)blockIdx.z * dstBS))[i4] = lv;
}

__global__ void wqkv_split_kernel(const float* __restrict__ Wq, const float* __restrict__ Wk,
                                  const float* __restrict__ Wv)
{
    const int t = blockIdx.x * 256 + threadIdx.x;
    float v;
    if (t < 64 * CC) v = Wq[t];
    else if (t < 128 * CC) v = Wk[t - 64 * CC];
    else v = Wv[t - 128 * CC];
    __nv_bfloat16 h, l;
    split1(v, h, l);
    g_Wqkvhi[t] = h; g_Wqkvlo[t] = l;
}

// ---------------- misc ----------------
__global__ void zero_kernel()
{
    const int t = blockIdx.x * 256 + threadIdx.x;
    if (t < CC) { g_sum[t] = 0.f; g_sumsq[t] = 0.f; }
    if (t < BB * NN) g_colsum[t] = 0.f;
}

__global__ void bn_finalize_kernel(const float* __restrict__ gamma, const float* __restrict__ beta)
{
    const int c = threadIdx.x;
    const float cnt = (float)(BB * NN);
    const float mean = g_sum[c] / cnt;
    const float var = g_sumsq[c] / cnt - mean * mean;
    const float sc = gamma[c] * rsqrtf(var + 1e-5f);
    g_scale[c] = sc;
    g_shift[c] = beta[c] - mean * sc;
}

__global__ void final_kernel(const float* __restrict__ x, float* __restrict__ out)
{
    const size_t idx = (size_t)blockIdx.x * 256 + threadIdx.x;
    const int c = (int)((idx >> 12) & (CC - 1));
    const float t = g_T[idx] * g_scale[c] + g_shift[c];
    out[idx] = x[idx] + fmaxf(t, 0.f);
}

// ---------------- launch ----------------
extern "C" void kernel_launch(void* const* d_in, const int* in_sizes, int n_in,
                              void* d_out, int out_size)
{
    const float* x     = (const float*)d_in[0];
    const float* Wq    = (const float*)d_in[1];
    const float* Wk    = (const float*)d_in[2];
    const float* Wv    = (const float*)d_in[3];
    const float* bv    = (const float*)d_in[4];
    const float* Wt    = (const float*)d_in[5];
    const float* bt    = (const float*)d_in[6];
    const float* gamma = (const float*)d_in[7];
    const float* beta  = (const float*)d_in[8];
    float* out = (float*)d_out;

    float *pT;
    __nv_bfloat16 *pA, *pXhi, *pXlo, *pVhi, *pVlo, *pDhi, *pDlo;
    __nv_bfloat16 *pQthi, *pQtlo, *pKhi, *pKlo, *pWqkvhi, *pWqkvlo, *pWthi, *pWtlo;
    cudaGetSymbolAddress((void**)&pT, g_T);
    cudaGetSymbolAddress((void**)&pA, g_A);
    cudaGetSymbolAddress((void**)&pXhi, g_xhi);
    cudaGetSymbolAddress((void**)&pXlo, g_xlo);
    cudaGetSymbolAddress((void**)&pVhi, g_Vhi);
    cudaGetSymbolAddress((void**)&pVlo, g_Vlo);
    cudaGetSymbolAddress((void**)&pDhi, g_dhi);
    cudaGetSymbolAddress((void**)&pDlo, g_dlo);
    cudaGetSymbolAddress((void**)&pQthi, g_Qthi);
    cudaGetSymbolAddress((void**)&pQtlo, g_Qtlo);
    cudaGetSymbolAddress((void**)&pKhi, g_Khi);
    cudaGetSymbolAddress((void**)&pKlo, g_Klo);
    cudaGetSymbolAddress((void**)&pWqkvhi, g_Wqkvhi);
    cudaGetSymbolAddress((void**)&pWqkvlo, g_Wqkvlo);
    cudaGetSymbolAddress((void**)&pWthi, g_Wthi);
    cudaGetSymbolAddress((void**)&pWtlo, g_Wtlo);

    const int attn_smem = (2 * 128 * QA_ST + 2 * 2 * 64 * KB_ST) * 2 + 128 * 4;
    cudaFuncSetAttribute(attn_kernel, cudaFuncAttributeMaxDynamicSharedMemorySize, attn_smem);

    // mma gemm dynamic smem: 4 stages
    const int smem_nb2 = 4 * (2 * 128 * SA_STRIDE * 2 + 2 * 16 * SB_STRIDE * 2);  // 83968
    const int smem_nb1 = 4 * (2 * 128 * SA_STRIDE * 2 + 1 * 16 * SB_STRIDE * 2);  // 66560
    cudaFuncSetAttribute(mma_gemm_kernel<2, 1>, cudaFuncAttributeMaxDynamicSharedMemorySize, smem_nb2);
    cudaFuncSetAttribute(mma_gemm_kernel<2, 2>, cudaFuncAttributeMaxDynamicSharedMemorySize, smem_nb2);
    cudaFuncSetAttribute(mma_gemm_kernel<1, 3>, cudaFuncAttributeMaxDynamicSharedMemorySize, smem_nb1);

    zero_kernel<<<BB * NN / 256, 256>>>();
    wqkv_split_kernel<<<384 * CC / 256, 256>>>(Wq, Wk, Wv);
    split4_kernel<<<dim3(CC * CC / 1024, 1, 1), 256>>>(Wt, 0, pWthi, pWtlo, 0);
    split4_kernel<<<dim3(CC * NN / 1024, 1, BB), 256>>>(x, (size_t)CC * NN, pXhi, pXlo, (size_t)CC * NN);

    // stacked QKV projection: [384,256] @ [256,4096]; epilogue writes Qt/K/V splits
    mma_gemm_kernel<2, 1><<<dim3(NN / 128, 3, BB), 256, smem_nb2>>>(
        pWqkvhi, pWqkvlo, CC, 0,
        pXhi, pXlo, (size_t)CC * NN,
        pT /*unused*/, 0, CC, bv, nullptr, 0);

    // fused energy + exp + rowsum -> U (bf16), invrs
    attn_kernel<<<dim3(NN / 128, BB), 256, attn_smem>>>();

    // V' = V * invrs[n] (in place)
    vrescale_kernel<<<dim3(CC * NN / 512, 1, BB), 256>>>();

    // weighted column sums for L1 renorm
    colsum_kernel<<<dim3(NN / 512, NN / 128, BB), 256>>>();

    // x_r = V' @ U; epilogue computes d = x - xr*colscale, writes d splits
    mma_gemm_kernel<1, 3><<<dim3(NN / 128, CC / 128, BB), 256, smem_nb1>>>(
        pVhi, pVlo, NN, (size_t)CC * NN,
        pA, nullptr, (size_t)NN * NN,
        pT /*unused*/, 0, NN, nullptr, x, (size_t)CC * NN);

    // t = Wt @ d + bt, with BN stats -> g_T
    mma_gemm_kernel<2, 2><<<dim3(NN / 128, CC / 128, BB), 256, smem_nb2>>>(
        pWthi, pWtlo, CC, 0,
        pDhi, pDlo, (size_t)CC * NN,
        pT, (size_t)CC * NN, CC, bt, nullptr, 0);

    bn_finalize_kernel<<<1, CC>>>(gamma, beta);

    final_kernel<<<(size_t)BB * CC * NN / 256, 256>>>(x, out);
}

// round 9
// speedup vs baseline: 1.5061x; 1.1486x over previous
#include <cuda_runtime.h>
#include <cuda_bf16.h>
#include <cstdint>

#define BB 4
#define CC 256
#define CQ 64
#define NN 4096

// ---------------- scratch (device globals; no allocations) ----------------
__device__ __nv_bfloat16 g_A[(size_t)BB * NN * NN];     // U = exp(E), bf16, unnormalized
__device__ __nv_bfloat16 g_xhi[(size_t)BB * CC * NN];
__device__ __nv_bfloat16 g_xlo[(size_t)BB * CC * NN];
__device__ float g_V[(size_t)BB * CC * NN];             // V fp32 (pre-rescale)
__device__ __nv_bfloat16 g_Vhi[(size_t)BB * CC * NN];   // V' = V*invrs, single bf16 plane
__device__ __nv_bfloat16 g_dhi[(size_t)BB * CC * NN];   // d = x - xr*colscale, split
__device__ __nv_bfloat16 g_dlo[(size_t)BB * CC * NN];
__device__ __nv_bfloat16 g_Qthi[(size_t)BB * NN * CQ];  // Q transposed [n][o]
__device__ __nv_bfloat16 g_Qtlo[(size_t)BB * NN * CQ];
__device__ __nv_bfloat16 g_Khi[(size_t)BB * CQ * NN];
__device__ __nv_bfloat16 g_Klo[(size_t)BB * CQ * NN];
__device__ __nv_bfloat16 g_Wqkvhi[384 * CC];            // Wq(64) ; Wk(64) ; Wv(256) rows
__device__ __nv_bfloat16 g_Wqkvlo[384 * CC];
__device__ __nv_bfloat16 g_Wthi[CC * CC];
__device__ __nv_bfloat16 g_Wtlo[CC * CC];
__device__ float g_T[(size_t)BB * CC * NN];
__device__ float g_invrs[BB * NN];                      // 1 / softmax row sums
__device__ float g_colsum[BB * NN];
__device__ float g_sum[CC];
__device__ float g_sumsq[CC];
__device__ float g_scale[CC];
__device__ float g_shift[CC];

// ---------------- PTX helpers ----------------
__device__ __forceinline__ void mma16816(float* c, const uint32_t* a, const uint32_t* b) {
    asm volatile(
        "mma.sync.aligned.m16n8k16.row.col.f32.bf16.bf16.f32 "
        "{%0,%1,%2,%3}, {%4,%5,%6,%7}, {%8,%9}, {%0,%1,%2,%3};\n"
        : "+f"(c[0]), "+f"(c[1]), "+f"(c[2]), "+f"(c[3])
        : "r"(a[0]), "r"(a[1]), "r"(a[2]), "r"(a[3]), "r"(b[0]), "r"(b[1]));
}
__device__ __forceinline__ void ldsm4(uint32_t* r, uint32_t addr) {
    asm volatile("ldmatrix.sync.aligned.m8n8.x4.shared.b16 {%0,%1,%2,%3}, [%4];"
        : "=r"(r[0]), "=r"(r[1]), "=r"(r[2]), "=r"(r[3]) : "r"(addr));
}
__device__ __forceinline__ void ldsm4t(uint32_t* r, uint32_t addr) {
    asm volatile("ldmatrix.sync.aligned.m8n8.x4.trans.shared.b16 {%0,%1,%2,%3}, [%4];"
        : "=r"(r[0]), "=r"(r[1]), "=r"(r[2]), "=r"(r[3]) : "r"(addr));
}
__device__ __forceinline__ void cpasync16(uint32_t saddr, const void* g) {
    asm volatile("cp.async.cg.shared.global [%0], [%1], 16;" :: "r"(saddr), "l"(g));
}
__device__ __forceinline__ void cp_commit() { asm volatile("cp.async.commit_group;" ::: "memory"); }

__device__ __forceinline__ void split1(float v, __nv_bfloat16& h, __nv_bfloat16& l) {
    h = __float2bfloat16(v);
    l = __float2bfloat16(v - __bfloat162float(h));
}
__device__ __forceinline__ void split_pack(float a, float b, __nv_bfloat162& hi2, __nv_bfloat162& lo2) {
    __nv_bfloat16 ha, la, hb, lb;
    split1(a, ha, la); split1(b, hb, lb);
    hi2.x = ha; hi2.y = hb;
    lo2.x = la; lo2.y = lb;
}

// ---------------- unified bf16-split tensor-core GEMM, 4-stage pipeline ----------------
// C[M,N] = (A0(+A1))[M,K] @ (B0(+B1))[K,N]     ldb = ldc = NN
// products emitted: a0b0 (+a0b1 if NB==2) (+a1b0 if NA==2)
// EPI 1 = stacked QKV projection epilogue (V stored fp32)
// EPI 2 = transform (+bias, BN stats)
// EPI 3 = xr->d: d = aux(x) - acc/(1e-9+colsum[col]), split store
#define SA_STRIDE 24
#define SB_STRIDE 136

template<int NA, int NB, int EPI>
__global__ __launch_bounds__(256)
void mma_gemm_kernel(const __nv_bfloat16* __restrict__ Ahi, const __nv_bfloat16* __restrict__ Alo,
                     int lda, size_t aBS,
                     const __nv_bfloat16* __restrict__ B0, const __nv_bfloat16* __restrict__ B1,
                     size_t bBS,
                     float* __restrict__ C, size_t cBS, int K,
                     const float* __restrict__ bias,
                     const float* __restrict__ aux, size_t auxBS)
{
    extern __shared__ __align__(16) char dynsm[];
    constexpr uint32_t A_PLANE = 128 * SA_STRIDE * 2;          // 6144
    constexpr uint32_t B_PLANE = 16 * SB_STRIDE * 2;           // 4352
    constexpr uint32_t STAGE   = NA * A_PLANE + NB * B_PLANE;

    const int bz = blockIdx.z;
    Ahi += (size_t)bz * aBS;
    if (NA == 2) Alo += (size_t)bz * aBS;
    B0  += (size_t)bz * bBS;
    if (NB == 2) B1 += (size_t)bz * bBS;
    C += (size_t)bz * cBS;
    if (EPI == 3) aux += (size_t)bz * auxBS;

    const int row0 = blockIdx.y * 128;
    const int col0 = blockIdx.x * 128;
    const int tid  = threadIdx.x;
    const int lane = tid & 31, warp = tid >> 5;
    const int wm = warp & 3;
    const int wn = warp >> 2;

    const int ar = tid >> 1, ac = (tid & 1) * 8;
    const int bk = tid >> 4, bc = (tid & 15) * 8;
    const size_t gA = (size_t)(row0 + ar) * lda + ac;
    const size_t gB = (size_t)bk * NN + col0 + bc;

    const uint32_t sbase = (uint32_t)__cvta_generic_to_shared(dynsm);
    const uint32_t sAst = (uint32_t)(ar * SA_STRIDE + ac) * 2;
    const uint32_t sBst = NA * A_PLANE + (uint32_t)(bk * SB_STRIDE + bc) * 2;

    float acc[2][8][4];
#pragma unroll
    for (int i = 0; i < 2; i++)
#pragma unroll
        for (int j = 0; j < 8; j++)
#pragma unroll
            for (int k = 0; k < 4; k++) acc[i][j][k] = 0.f;

    const int KT = K >> 4;

    auto issue = [&](int kt, int s) {
        const size_t ka = gA + (size_t)kt * 16;
        const size_t kb = gB + (size_t)kt * 16 * NN;
        const uint32_t st = sbase + (uint32_t)s * STAGE;
        cpasync16(st + sAst, Ahi + ka);
        if (NA == 2) cpasync16(st + A_PLANE + sAst, Alo + ka);
        cpasync16(st + sBst, B0 + kb);
        if (NB == 2) cpasync16(st + B_PLANE + sBst, B1 + kb);
    };

    // prologue: 3 tiles in flight
#pragma unroll
    for (int s = 0; s < 3; s++) { issue(s, s); cp_commit(); }

    const int lr = lane & 15, lc8 = (lane >> 4) * 8;
    const uint32_t aOff = ((wm * 32 + lr) * SA_STRIDE + lc8) * 2;
    const uint32_t bOff = NA * A_PLANE + (lr * SB_STRIDE + wn * 64 + lc8) * 2;

    for (int kt = 0; kt < KT; kt++) {
        asm volatile("cp.async.wait_group 2;" ::: "memory");
        __syncthreads();
        // keep group accounting exact with empty commits at the tail
        if (kt + 3 < KT) issue(kt + 3, (kt + 3) & 3);
        cp_commit();

        const uint32_t st = sbase + (uint32_t)(kt & 3) * STAGE;

        uint32_t ah[2][4], al[2][4];
#pragma unroll
        for (int mi = 0; mi < 2; mi++) {
            ldsm4(ah[mi], st + aOff + mi * 16 * SA_STRIDE * 2);
            if (NA == 2) ldsm4(al[mi], st + A_PLANE + aOff + mi * 16 * SA_STRIDE * 2);
        }
        uint32_t bh[4][4], bl[4][4];
#pragma unroll
        for (int j = 0; j < 4; j++) {
            ldsm4t(bh[j], st + bOff + j * 16 * 2);
            if (NB == 2) ldsm4t(bl[j], st + bOff + B_PLANE + j * 16 * 2);
        }
#pragma unroll
        for (int mi = 0; mi < 2; mi++) {
#pragma unroll
            for (int j = 0; j < 4; j++) {
                mma16816(acc[mi][2 * j],     ah[mi], &bh[j][0]);
                mma16816(acc[mi][2 * j + 1], ah[mi], &bh[j][2]);
                if (NB == 2) {
                    mma16816(acc[mi][2 * j],     ah[mi], &bl[j][0]);
                    mma16816(acc[mi][2 * j + 1], ah[mi], &bl[j][2]);
                }
                if (NA == 2) {
                    mma16816(acc[mi][2 * j],     al[mi], &bh[j][0]);
                    mma16816(acc[mi][2 * j + 1], al[mi], &bh[j][2]);
                }
            }
        }
        // no trailing sync: top-of-loop barrier protects buffer reuse
    }

    const int gid = lane >> 2, t4 = lane & 3;

    if (EPI == 1) {
        const int by = blockIdx.y;
#pragma unroll
        for (int mi = 0; mi < 2; mi++)
#pragma unroll
            for (int nj = 0; nj < 8; nj++) {
                const int r = row0 + wm * 32 + mi * 16 + gid;
                const int col = col0 + wn * 64 + nj * 8 + t4 * 2;
                const float v00 = acc[mi][nj][0], v01 = acc[mi][nj][1];
                const float v10 = acc[mi][nj][2], v11 = acc[mi][nj][3];
                if (by == 0) {
                    if (r < 64) {  // Q -> transposed split [n][o]
                        const size_t base = (size_t)bz * NN * CQ;
                        __nv_bfloat16 h, l;
                        split1(v00, h, l); g_Qthi[base + (size_t)col * CQ + r] = h;       g_Qtlo[base + (size_t)col * CQ + r] = l;
                        split1(v01, h, l); g_Qthi[base + (size_t)(col + 1) * CQ + r] = h; g_Qtlo[base + (size_t)(col + 1) * CQ + r] = l;
                        split1(v10, h, l); g_Qthi[base + (size_t)col * CQ + r + 8] = h;       g_Qtlo[base + (size_t)col * CQ + r + 8] = l;
                        split1(v11, h, l); g_Qthi[base + (size_t)(col + 1) * CQ + r + 8] = h; g_Qtlo[base + (size_t)(col + 1) * CQ + r + 8] = l;
                    } else {       // K -> split [o][n]
                        const int kr = r - 64;
                        const size_t base = (size_t)bz * CQ * NN;
                        __nv_bfloat162 h2, l2;
                        split_pack(v00, v01, h2, l2);
                        *(__nv_bfloat162*)&g_Khi[base + (size_t)kr * NN + col] = h2;
                        *(__nv_bfloat162*)&g_Klo[base + (size_t)kr * NN + col] = l2;
                        split_pack(v10, v11, h2, l2);
                        *(__nv_bfloat162*)&g_Khi[base + (size_t)(kr + 8) * NN + col] = h2;
                        *(__nv_bfloat162*)&g_Klo[base + (size_t)(kr + 8) * NN + col] = l2;
                    }
                } else {           // V rows (+bias) -> fp32 (single rounding happens in vrescale)
                    const int vr = r - 128;
                    float* dst = g_V + (size_t)bz * CC * NN;
                    const float b0 = bias[vr], b1 = bias[vr + 8];
                    *(float2*)&dst[(size_t)vr * NN + col]       = make_float2(v00 + b0, v01 + b0);
                    *(float2*)&dst[(size_t)(vr + 8) * NN + col] = make_float2(v10 + b1, v11 + b1);
                }
            }
    }

    if (EPI == 2) {
        float ssum[2][2] = {{0.f, 0.f}, {0.f, 0.f}};
        float ssq[2][2]  = {{0.f, 0.f}, {0.f, 0.f}};
#pragma unroll
        for (int mi = 0; mi < 2; mi++)
#pragma unroll
            for (int nj = 0; nj < 8; nj++) {
                const int r = row0 + wm * 32 + mi * 16 + gid;
                const int col = col0 + wn * 64 + nj * 8 + t4 * 2;
                const float b0 = bias[r], b1 = bias[r + 8];
                const float v00 = acc[mi][nj][0] + b0, v01 = acc[mi][nj][1] + b0;
                const float v10 = acc[mi][nj][2] + b1, v11 = acc[mi][nj][3] + b1;
                *(float2*)&C[(size_t)r * NN + col]       = make_float2(v00, v01);
                *(float2*)&C[(size_t)(r + 8) * NN + col] = make_float2(v10, v11);
                ssum[mi][0] += v00 + v01;  ssq[mi][0] += v00 * v00 + v01 * v01;
                ssum[mi][1] += v10 + v11;  ssq[mi][1] += v10 * v10 + v11 * v11;
            }
#pragma unroll
        for (int mi = 0; mi < 2; mi++)
#pragma unroll
            for (int h = 0; h < 2; h++) {
                const int r = row0 + wm * 32 + mi * 16 + gid + h * 8;
                atomicAdd(&g_sum[r], ssum[mi][h]);
                atomicAdd(&g_sumsq[r], ssq[mi][h]);
            }
    }

    if (EPI == 3) {
#pragma unroll
        for (int mi = 0; mi < 2; mi++)
#pragma unroll
            for (int nj = 0; nj < 8; nj++) {
                const int r = row0 + wm * 32 + mi * 16 + gid;
                const int col = col0 + wn * 64 + nj * 8 + t4 * 2;
                const float cs0 = 1.0f / (1e-9f + g_colsum[bz * NN + col]);
                const float cs1 = 1.0f / (1e-9f + g_colsum[bz * NN + col + 1]);
                const size_t base = (size_t)bz * CC * NN;
                const float d00 = aux[(size_t)r * NN + col]       - acc[mi][nj][0] * cs0;
                const float d01 = aux[(size_t)r * NN + col + 1]   - acc[mi][nj][1] * cs1;
                const float d10 = aux[(size_t)(r + 8) * NN + col]     - acc[mi][nj][2] * cs0;
                const float d11 = aux[(size_t)(r + 8) * NN + col + 1] - acc[mi][nj][3] * cs1;
                __nv_bfloat162 h2, l2;
                split_pack(d00, d01, h2, l2);
                *(__nv_bfloat162*)&g_dhi[base + (size_t)r * NN + col] = h2;
                *(__nv_bfloat162*)&g_dlo[base + (size_t)r * NN + col] = l2;
                split_pack(d10, d11, h2, l2);
                *(__nv_bfloat162*)&g_dhi[base + (size_t)(r + 8) * NN + col] = h2;
                *(__nv_bfloat162*)&g_dlo[base + (size_t)(r + 8) * NN + col] = l2;
            }
    }
}

// ---------------- fused energy + exp + rowsum -> U bf16 ----------------
#define QA_ST 72
#define KB_ST 136

__global__ __launch_bounds__(256)
void attn_kernel()
{
    extern __shared__ __align__(16) char dsm[];
    __nv_bfloat16* sQ = (__nv_bfloat16*)dsm;
    __nv_bfloat16* sK = sQ + 2 * 128 * QA_ST;
    float* s_rs = (float*)(sK + 2 * 2 * 64 * KB_ST);

    const int b  = blockIdx.y;
    const int r0 = blockIdx.x * 128;
    const int tid = threadIdx.x;
    const int lane = tid & 31, warp = tid >> 5;
    const int wm = warp & 3, wn = warp >> 2;

    if (tid < 128) s_rs[tid] = 0.f;

    const uint32_t sQb = (uint32_t)__cvta_generic_to_shared(sQ);
    const uint32_t sKb = (uint32_t)__cvta_generic_to_shared(sK);

    const __nv_bfloat16* Qhi = g_Qthi + (size_t)b * NN * CQ;
    const __nv_bfloat16* Qlo = g_Qtlo + (size_t)b * NN * CQ;
#pragma unroll
    for (int p = 0; p < 4; p++) {
        const int idx = p * 256 + tid;
        const int row = idx >> 3, c8 = (idx & 7) * 8;
        cpasync16(sQb + (uint32_t)(row * QA_ST + c8) * 2,
                  Qhi + (size_t)(r0 + row) * CQ + c8);
        cpasync16(sQb + (uint32_t)(128 * QA_ST + row * QA_ST + c8) * 2,
                  Qlo + (size_t)(r0 + row) * CQ + c8);
    }
    cp_commit();

    const __nv_bfloat16* Khi = g_Khi + (size_t)b * CQ * NN;
    const __nv_bfloat16* Klo = g_Klo + (size_t)b * CQ * NN;
    const int kr = tid >> 4, kc8 = (tid & 15) * 8;

    auto issueK = [&](int tile, int stage) {
        const int c0 = tile * 128;
        const uint32_t base = sKb + (uint32_t)stage * (2 * 64 * KB_ST * 2);
#pragma unroll
        for (int c = 0; c < 4; c++) {
            const int r = kr + c * 16;
            cpasync16(base + (uint32_t)(r * KB_ST + kc8) * 2,
                      Khi + (size_t)r * NN + c0 + kc8);
            cpasync16(base + (uint32_t)(64 * KB_ST + r * KB_ST + kc8) * 2,
                      Klo + (size_t)r * NN + c0 + kc8);
        }
        cp_commit();
    };

    issueK(0, 0);

    const int lr = lane & 15, lc8 = (lane >> 4) * 8;
    const uint32_t aBase = sQb + (uint32_t)((wm * 32 + lr) * QA_ST + lc8) * 2;
    const uint32_t bBase = sKb + (uint32_t)(lr * KB_ST + wn * 64 + lc8) * 2;
    constexpr uint32_t QPLANE = 128 * QA_ST * 2;
    constexpr uint32_t KPLANE = 64 * KB_ST * 2;
    constexpr uint32_t KSTAGE = 2 * KPLANE;

    const int gid = lane >> 2, t4 = lane & 3;
    float rowsum[2][2] = {{0.f, 0.f}, {0.f, 0.f}};
    __nv_bfloat16* U = g_A + (size_t)b * NN * NN;

    for (int tile = 0; tile < 32; tile++) {
        const int cur = tile & 1;
        if (tile + 1 < 32) {
            issueK(tile + 1, cur ^ 1);
            asm volatile("cp.async.wait_group 1;" ::: "memory");
        } else {
            asm volatile("cp.async.wait_group 0;" ::: "memory");
        }
        __syncthreads();

        const uint32_t bS = cur * KSTAGE;

        float acc[2][8][4];
#pragma unroll
        for (int i = 0; i < 2; i++)
#pragma unroll
            for (int j = 0; j < 8; j++)
#pragma unroll
                for (int k = 0; k < 4; k++) acc[i][j][k] = 0.f;

#pragma unroll
        for (int ch = 0; ch < 4; ch++) {
            uint32_t ah[2][4], al[2][4];
#pragma unroll
            for (int mi = 0; mi < 2; mi++) {
                ldsm4(ah[mi], aBase + ch * 32 + mi * 16 * QA_ST * 2);
                ldsm4(al[mi], aBase + QPLANE + ch * 32 + mi * 16 * QA_ST * 2);
            }
            uint32_t bh[4][4], bl[4][4];
#pragma unroll
            for (int j = 0; j < 4; j++) {
                ldsm4t(bh[j], bBase + bS + ch * 16 * KB_ST * 2 + j * 16 * 2);
                ldsm4t(bl[j], bBase + bS + KPLANE + ch * 16 * KB_ST * 2 + j * 16 * 2);
            }
#pragma unroll
            for (int mi = 0; mi < 2; mi++)
#pragma unroll
                for (int j = 0; j < 4; j++) {
                    mma16816(acc[mi][2 * j],     ah[mi], &bh[j][0]);
                    mma16816(acc[mi][2 * j + 1], ah[mi], &bh[j][2]);
                    mma16816(acc[mi][2 * j],     ah[mi], &bl[j][0]);
                    mma16816(acc[mi][2 * j + 1], ah[mi], &bl[j][2]);
                    mma16816(acc[mi][2 * j],     al[mi], &bh[j][0]);
                    mma16816(acc[mi][2 * j + 1], al[mi], &bh[j][2]);
                }
        }

        const int c0 = tile * 128;
#pragma unroll
        for (int mi = 0; mi < 2; mi++)
#pragma unroll
            for (int nj = 0; nj < 8; nj++) {
                const int row = r0 + wm * 32 + mi * 16 + gid;
                const int col = c0 + wn * 64 + nj * 8 + t4 * 2;
                const float e00 = __expf(acc[mi][nj][0]);
                const float e01 = __expf(acc[mi][nj][1]);
                const float e10 = __expf(acc[mi][nj][2]);
                const float e11 = __expf(acc[mi][nj][3]);
                rowsum[mi][0] += e00 + e01;
                rowsum[mi][1] += e10 + e11;
                __nv_bfloat162 p0, p1;
                p0.x = __float2bfloat16(e00); p0.y = __float2bfloat16(e01);
                p1.x = __float2bfloat16(e10); p1.y = __float2bfloat16(e11);
                *(__nv_bfloat162*)&U[(size_t)row * NN + col] = p0;
                *(__nv_bfloat162*)&U[(size_t)(row + 8) * NN + col] = p1;
            }
        __syncthreads();
    }

#pragma unroll
    for (int mi = 0; mi < 2; mi++)
#pragma unroll
        for (int h = 0; h < 2; h++) {
            float v = rowsum[mi][h];
            v += __shfl_xor_sync(0xffffffffu, v, 1);
            v += __shfl_xor_sync(0xffffffffu, v, 2);
            if (t4 == 0) atomicAdd(&s_rs[wm * 32 + mi * 16 + gid + h * 8], v);
        }
    __syncthreads();
    if (tid < 128) g_invrs[b * NN + r0 + tid] = 1.0f / s_rs[tid];
}

// ---------------- V' = V_fp32 * invrs[n] -> single bf16 plane ----------------
__global__ void vrescale_kernel()
{
    const int b = blockIdx.z;
    const size_t i4 = (size_t)blockIdx.x * 256 + threadIdx.x;   // over CC*NN/4
    const float4 v = ((const float4*)(g_V + (size_t)b * CC * NN))[i4];
    const int n4 = (int)((i4 * 4) & (NN - 1));
    const float4 w = *(const float4*)&g_invrs[b * NN + n4];
    __nv_bfloat162 p0, p1;
    p0.x = __float2bfloat16(v.x * w.x); p0.y = __float2bfloat16(v.y * w.y);
    p1.x = __float2bfloat16(v.z * w.z); p1.y = __float2bfloat16(v.w * w.w);
    uint2 o;
    o.x = *(uint32_t*)&p0; o.y = *(uint32_t*)&p1;
    ((uint2*)(g_Vhi + (size_t)b * CC * NN))[i4] = o;
}

// ---------------- weighted column sums ----------------
__global__ void colsum_kernel()
{
    const int m2 = blockIdx.x * 256 + threadIdx.x;
    const int b = blockIdx.z;
    const int n0 = blockIdx.y * 128;
    const __nv_bfloat162* A2 = (const __nv_bfloat162*)(g_A + (size_t)b * NN * NN);
    float s0 = 0.f, s1 = 0.f;
#pragma unroll 4
    for (int n = 0; n < 128; n++) {
        const float w = g_invrs[b * NN + n0 + n];
        const __nv_bfloat162 a = A2[(size_t)(n0 + n) * (NN / 2) + m2];
        s0 += __bfloat162float(a.x) * w;
        s1 += __bfloat162float(a.y) * w;
    }
    atomicAdd(&g_colsum[b * NN + 2 * m2 + 0], s0);
    atomicAdd(&g_colsum[b * NN + 2 * m2 + 1], s1);
}

// ---------------- splits ----------------
__global__ void split4_kernel(const float* __restrict__ src, size_t srcBS,
                              __nv_bfloat16* __restrict__ hi, __nv_bfloat16* __restrict__ lo,
                              size_t dstBS)
{
    const size_t i4 = (size_t)blockIdx.x * 256 + threadIdx.x;
    const float4 v = ((const float4*)(src + (size_t)blockIdx.z * srcBS))[i4];
    __nv_bfloat162 ha, la, hb, lb;
    split_pack(v.x, v.y, ha, la);
    split_pack(v.z, v.w, hb, lb);
    uint2 hv, lv;
    hv.x = *(uint32_t*)&ha; hv.y = *(uint32_t*)&hb;
    lv.x = *(uint32_t*)&la; lv.y = *(uint32_t*)&lb;
    ((uint2*)(hi + (size_t)blockIdx.z * dstBS))[i4] = hv;
    ((uint2*)(lo + (size_t)blockIdx.z * dstBS))[i4] = lv;
}

__global__ void wqkv_split_kernel(const float* __restrict__ Wq, const float* __restrict__ Wk,
                                  const float* __restrict__ Wv)
{
    const int t = blockIdx.x * 256 + threadIdx.x;
    float v;
    if (t < 64 * CC) v = Wq[t];
    else if (t < 128 * CC) v = Wk[t - 64 * CC];
    else v = Wv[t - 128 * CC];
    __nv_bfloat16 h, l;
    split1(v, h, l);
    g_Wqkvhi[t] = h; g_Wqkvlo[t] = l;
}

// ---------------- misc ----------------
__global__ void zero_kernel()
{
    const int t = blockIdx.x * 256 + threadIdx.x;
    if (t < CC) { g_sum[t] = 0.f; g_sumsq[t] = 0.f; }
    if (t < BB * NN) g_colsum[t] = 0.f;
}

__global__ void bn_finalize_kernel(const float* __restrict__ gamma, const float* __restrict__ beta)
{
    const int c = threadIdx.x;
    const float cnt = (float)(BB * NN);
    const float mean = g_sum[c] / cnt;
    const float var = g_sumsq[c] / cnt - mean * mean;
    const float sc = gamma[c] * rsqrtf(var + 1e-5f);
    g_scale[c] = sc;
    g_shift[c] = beta[c] - mean * sc;
}

__global__ void final_kernel(const float* __restrict__ x, float* __restrict__ out)
{
    const size_t idx = (size_t)blockIdx.x * 256 + threadIdx.x;
    const int c = (int)((idx >> 12) & (CC - 1));
    const float t = g_T[idx] * g_scale[c] + g_shift[c];
    out[idx] = x[idx] + fmaxf(t, 0.f);
}

// ---------------- launch ----------------
extern "C" void kernel_launch(void* const* d_in, const int* in_sizes, int n_in,
                              void* d_out, int out_size)
{
    const float* x     = (const float*)d_in[0];
    const float* Wq    = (const float*)d_in[1];
    const float* Wk    = (const float*)d_in[2];
    const float* Wv    = (const float*)d_in[3];
    const float* bv    = (const float*)d_in[4];
    const float* Wt    = (const float*)d_in[5];
    const float* bt    = (const float*)d_in[6];
    const float* gamma = (const float*)d_in[7];
    const float* beta  = (const float*)d_in[8];
    float* out = (float*)d_out;

    float *pT;
    __nv_bfloat16 *pA, *pXhi, *pXlo, *pVhi, *pDhi, *pDlo;
    __nv_bfloat16 *pWqkvhi, *pWqkvlo, *pWthi, *pWtlo;
    cudaGetSymbolAddress((void**)&pT, g_T);
    cudaGetSymbolAddress((void**)&pA, g_A);
    cudaGetSymbolAddress((void**)&pXhi, g_xhi);
    cudaGetSymbolAddress((void**)&pXlo, g_xlo);
    cudaGetSymbolAddress((void**)&pVhi, g_Vhi);
    cudaGetSymbolAddress((void**)&pDhi, g_dhi);
    cudaGetSymbolAddress((void**)&pDlo, g_dlo);
    cudaGetSymbolAddress((void**)&pWqkvhi, g_Wqkvhi);
    cudaGetSymbolAddress((void**)&pWqkvlo, g_Wqkvlo);
    cudaGetSymbolAddress((void**)&pWthi, g_Wthi);
    cudaGetSymbolAddress((void**)&pWtlo, g_Wtlo);

    const int attn_smem = (2 * 128 * QA_ST + 2 * 2 * 64 * KB_ST) * 2 + 128 * 4;
    cudaFuncSetAttribute(attn_kernel, cudaFuncAttributeMaxDynamicSharedMemorySize, attn_smem);

    // mma gemm dynamic smem: 4 stages
    const int smem_22 = 4 * (2 * 128 * SA_STRIDE * 2 + 2 * 16 * SB_STRIDE * 2);  // 83968
    const int smem_11 = 4 * (1 * 128 * SA_STRIDE * 2 + 1 * 16 * SB_STRIDE * 2);  // 41984
    cudaFuncSetAttribute(mma_gemm_kernel<2, 2, 1>, cudaFuncAttributeMaxDynamicSharedMemorySize, smem_22);
    cudaFuncSetAttribute(mma_gemm_kernel<2, 2, 2>, cudaFuncAttributeMaxDynamicSharedMemorySize, smem_22);
    cudaFuncSetAttribute(mma_gemm_kernel<1, 1, 3>, cudaFuncAttributeMaxDynamicSharedMemorySize, smem_11);

    zero_kernel<<<BB * NN / 256, 256>>>();
    wqkv_split_kernel<<<384 * CC / 256, 256>>>(Wq, Wk, Wv);
    split4_kernel<<<dim3(CC * CC / 1024, 1, 1), 256>>>(Wt, 0, pWthi, pWtlo, 0);
    split4_kernel<<<dim3(CC * NN / 1024, 1, BB), 256>>>(x, (size_t)CC * NN, pXhi, pXlo, (size_t)CC * NN);

    // stacked QKV projection: [384,256] @ [256,4096]; epilogue writes Qt/K splits + V fp32
    mma_gemm_kernel<2, 2, 1><<<dim3(NN / 128, 3, BB), 256, smem_22>>>(
        pWqkvhi, pWqkvlo, CC, 0,
        pXhi, pXlo, (size_t)CC * NN,
        pT /*unused*/, 0, CC, bv, nullptr, 0);

    // fused energy + exp + rowsum -> U (bf16), invrs
    attn_kernel<<<dim3(NN / 128, BB), 256, attn_smem>>>();

    // V' = V_fp32 * invrs[n] -> single bf16 plane
    vrescale_kernel<<<dim3(CC * NN / 1024, 1, BB), 256>>>();

    // weighted column sums for L1 renorm
    colsum_kernel<<<dim3(NN / 512, NN / 128, BB), 256>>>();

    // x_r = V' @ U (single-product); epilogue computes d = x - xr*colscale, writes d splits
    mma_gemm_kernel<1, 1, 3><<<dim3(NN / 128, CC / 128, BB), 256, smem_11>>>(
        pVhi, nullptr, NN, (size_t)CC * NN,
        pA, nullptr, (size_t)NN * NN,
        pT /*unused*/, 0, NN, nullptr, x, (size_t)CC * NN);

    // t = Wt @ d + bt, with BN stats -> g_T
    mma_gemm_kernel<2, 2, 2><<<dim3(NN / 128, CC / 128, BB), 256, smem_22>>>(
        pWthi, pWtlo, CC, 0,
        pDhi, pDlo, (size_t)CC * NN,
        pT, (size_t)CC * NN, CC, bt, nullptr, 0);

    bn_finalize_kernel<<<1, CC>>>(gamma, beta);

    final_kernel<<<(size_t)BB * CC * NN / 256, 256>>>(x, out);
}

// round 10
// speedup vs baseline: 1.6022x; 1.0638x over previous
#include <cuda_runtime.h>
#include <cuda_bf16.h>
#include <cstdint>

#define BB 4
#define CC 256
#define CQ 64
#define NN 4096

// ---------------- scratch (device globals; no allocations) ----------------
__device__ __nv_bfloat16 g_A[(size_t)BB * NN * NN];     // U = exp(E), bf16, unnormalized
__device__ __nv_bfloat16 g_xhi[(size_t)BB * CC * NN];
__device__ __nv_bfloat16 g_xlo[(size_t)BB * CC * NN];
__device__ float g_V[(size_t)BB * CC * NN];             // V fp32 (pre-rescale)
__device__ __nv_bfloat16 g_Vhi[(size_t)BB * CC * NN];   // V' = V*invrs, single bf16 plane
__device__ __nv_bfloat16 g_dhi[(size_t)BB * CC * NN];   // d = x - xr*colscale, split
__device__ __nv_bfloat16 g_dlo[(size_t)BB * CC * NN];
__device__ __nv_bfloat16 g_Qthi[(size_t)BB * NN * CQ];  // Q transposed [n][o]
__device__ __nv_bfloat16 g_Qtlo[(size_t)BB * NN * CQ];
__device__ __nv_bfloat16 g_Khi[(size_t)BB * CQ * NN];
__device__ __nv_bfloat16 g_Klo[(size_t)BB * CQ * NN];
__device__ __nv_bfloat16 g_Wqkvhi[384 * CC];            // Wq(64) ; Wk(64) ; Wv(256) rows
__device__ __nv_bfloat16 g_Wqkvlo[384 * CC];
__device__ __nv_bfloat16 g_Wthi[CC * CC];
__device__ __nv_bfloat16 g_Wtlo[CC * CC];
__device__ float g_T[(size_t)BB * CC * NN];
__device__ float g_rspart[8 * BB * NN];                 // per-colgroup rowsum partials
__device__ float g_invrs[BB * NN];                      // 1 / softmax row sums
__device__ float g_colsum[BB * NN];
__device__ float g_sum[CC];
__device__ float g_sumsq[CC];
__device__ float g_scale[CC];
__device__ float g_shift[CC];

// ---------------- PTX helpers ----------------
__device__ __forceinline__ void mma16816(float* c, const uint32_t* a, const uint32_t* b) {
    asm volatile(
        "mma.sync.aligned.m16n8k16.row.col.f32.bf16.bf16.f32 "
        "{%0,%1,%2,%3}, {%4,%5,%6,%7}, {%8,%9}, {%0,%1,%2,%3};\n"
        : "+f"(c[0]), "+f"(c[1]), "+f"(c[2]), "+f"(c[3])
        : "r"(a[0]), "r"(a[1]), "r"(a[2]), "r"(a[3]), "r"(b[0]), "r"(b[1]));
}
__device__ __forceinline__ void ldsm4(uint32_t* r, uint32_t addr) {
    asm volatile("ldmatrix.sync.aligned.m8n8.x4.shared.b16 {%0,%1,%2,%3}, [%4];"
        : "=r"(r[0]), "=r"(r[1]), "=r"(r[2]), "=r"(r[3]) : "r"(addr));
}
__device__ __forceinline__ void ldsm4t(uint32_t* r, uint32_t addr) {
    asm volatile("ldmatrix.sync.aligned.m8n8.x4.trans.shared.b16 {%0,%1,%2,%3}, [%4];"
        : "=r"(r[0]), "=r"(r[1]), "=r"(r[2]), "=r"(r[3]) : "r"(addr));
}
__device__ __forceinline__ void cpasync16(uint32_t saddr, const void* g) {
    asm volatile("cp.async.cg.shared.global [%0], [%1], 16;" :: "r"(saddr), "l"(g));
}
__device__ __forceinline__ void cp_commit() { asm volatile("cp.async.commit_group;" ::: "memory"); }

__device__ __forceinline__ void split1(float v, __nv_bfloat16& h, __nv_bfloat16& l) {
    h = __float2bfloat16(v);
    l = __float2bfloat16(v - __bfloat162float(h));
}
__device__ __forceinline__ void split_pack(float a, float b, __nv_bfloat162& hi2, __nv_bfloat162& lo2) {
    __nv_bfloat16 ha, la, hb, lb;
    split1(a, ha, la); split1(b, hb, lb);
    hi2.x = ha; hi2.y = hb;
    lo2.x = la; lo2.y = lb;
}

// ---------------- unified bf16-split tensor-core GEMM, 4-stage pipeline ----------------
// C[M,N] = (A0(+A1))[M,K] @ (B0(+B1))[K,N]     ldb = ldc = NN
// products emitted: a0b0 (+a0b1 if NB==2) (+a1b0 if NA==2)
// EPI 1 = stacked QKV projection epilogue (V stored fp32)
// EPI 2 = transform (+bias, BN stats)
// EPI 3 = xr->d: d = aux(x) - acc/(1e-9+colsum[col]), split store
#define SA_STRIDE 24
#define SB_STRIDE 136

template<int NA, int NB, int EPI>
__global__ __launch_bounds__(256)
void mma_gemm_kernel(const __nv_bfloat16* __restrict__ Ahi, const __nv_bfloat16* __restrict__ Alo,
                     int lda, size_t aBS,
                     const __nv_bfloat16* __restrict__ B0, const __nv_bfloat16* __restrict__ B1,
                     size_t bBS,
                     float* __restrict__ C, size_t cBS, int K,
                     const float* __restrict__ bias,
                     const float* __restrict__ aux, size_t auxBS)
{
    extern __shared__ __align__(16) char dynsm[];
    constexpr uint32_t A_PLANE = 128 * SA_STRIDE * 2;          // 6144
    constexpr uint32_t B_PLANE = 16 * SB_STRIDE * 2;           // 4352
    constexpr uint32_t STAGE   = NA * A_PLANE + NB * B_PLANE;

    const int bz = blockIdx.z;
    Ahi += (size_t)bz * aBS;
    if (NA == 2) Alo += (size_t)bz * aBS;
    B0  += (size_t)bz * bBS;
    if (NB == 2) B1 += (size_t)bz * bBS;
    C += (size_t)bz * cBS;
    if (EPI == 3) aux += (size_t)bz * auxBS;

    const int row0 = blockIdx.y * 128;
    const int col0 = blockIdx.x * 128;
    const int tid  = threadIdx.x;
    const int lane = tid & 31, warp = tid >> 5;
    const int wm = warp & 3;
    const int wn = warp >> 2;

    const int ar = tid >> 1, ac = (tid & 1) * 8;
    const int bk = tid >> 4, bc = (tid & 15) * 8;
    const size_t gA = (size_t)(row0 + ar) * lda + ac;
    const size_t gB = (size_t)bk * NN + col0 + bc;

    const uint32_t sbase = (uint32_t)__cvta_generic_to_shared(dynsm);
    const uint32_t sAst = (uint32_t)(ar * SA_STRIDE + ac) * 2;
    const uint32_t sBst = NA * A_PLANE + (uint32_t)(bk * SB_STRIDE + bc) * 2;

    float acc[2][8][4];
#pragma unroll
    for (int i = 0; i < 2; i++)
#pragma unroll
        for (int j = 0; j < 8; j++)
#pragma unroll
            for (int k = 0; k < 4; k++) acc[i][j][k] = 0.f;

    const int KT = K >> 4;

    auto issue = [&](int kt, int s) {
        const size_t ka = gA + (size_t)kt * 16;
        const size_t kb = gB + (size_t)kt * 16 * NN;
        const uint32_t st = sbase + (uint32_t)s * STAGE;
        cpasync16(st + sAst, Ahi + ka);
        if (NA == 2) cpasync16(st + A_PLANE + sAst, Alo + ka);
        cpasync16(st + sBst, B0 + kb);
        if (NB == 2) cpasync16(st + B_PLANE + sBst, B1 + kb);
    };

    // prologue: 3 tiles in flight
#pragma unroll
    for (int s = 0; s < 3; s++) { issue(s, s); cp_commit(); }

    const int lr = lane & 15, lc8 = (lane >> 4) * 8;
    const uint32_t aOff = ((wm * 32 + lr) * SA_STRIDE + lc8) * 2;
    const uint32_t bOff = NA * A_PLANE + (lr * SB_STRIDE + wn * 64 + lc8) * 2;

    for (int kt = 0; kt < KT; kt++) {
        asm volatile("cp.async.wait_group 2;" ::: "memory");
        __syncthreads();
        // keep group accounting exact with empty commits at the tail
        if (kt + 3 < KT) issue(kt + 3, (kt + 3) & 3);
        cp_commit();

        const uint32_t st = sbase + (uint32_t)(kt & 3) * STAGE;

        uint32_t ah[2][4], al[2][4];
#pragma unroll
        for (int mi = 0; mi < 2; mi++) {
            ldsm4(ah[mi], st + aOff + mi * 16 * SA_STRIDE * 2);
            if (NA == 2) ldsm4(al[mi], st + A_PLANE + aOff + mi * 16 * SA_STRIDE * 2);
        }
        uint32_t bh[4][4], bl[4][4];
#pragma unroll
        for (int j = 0; j < 4; j++) {
            ldsm4t(bh[j], st + bOff + j * 16 * 2);
            if (NB == 2) ldsm4t(bl[j], st + bOff + B_PLANE + j * 16 * 2);
        }
#pragma unroll
        for (int mi = 0; mi < 2; mi++) {
#pragma unroll
            for (int j = 0; j < 4; j++) {
                mma16816(acc[mi][2 * j],     ah[mi], &bh[j][0]);
                mma16816(acc[mi][2 * j + 1], ah[mi], &bh[j][2]);
                if (NB == 2) {
                    mma16816(acc[mi][2 * j],     ah[mi], &bl[j][0]);
                    mma16816(acc[mi][2 * j + 1], ah[mi], &bl[j][2]);
                }
                if (NA == 2) {
                    mma16816(acc[mi][2 * j],     al[mi], &bh[j][0]);
                    mma16816(acc[mi][2 * j + 1], al[mi], &bh[j][2]);
                }
            }
        }
        // no trailing sync: top-of-loop barrier protects buffer reuse
    }

    const int gid = lane >> 2, t4 = lane & 3;

    if (EPI == 1) {
        const int by = blockIdx.y;
#pragma unroll
        for (int mi = 0; mi < 2; mi++)
#pragma unroll
            for (int nj = 0; nj < 8; nj++) {
                const int r = row0 + wm * 32 + mi * 16 + gid;
                const int col = col0 + wn * 64 + nj * 8 + t4 * 2;
                const float v00 = acc[mi][nj][0], v01 = acc[mi][nj][1];
                const float v10 = acc[mi][nj][2], v11 = acc[mi][nj][3];
                if (by == 0) {
                    if (r < 64) {  // Q -> transposed split [n][o]
                        const size_t base = (size_t)bz * NN * CQ;
                        __nv_bfloat16 h, l;
                        split1(v00, h, l); g_Qthi[base + (size_t)col * CQ + r] = h;       g_Qtlo[base + (size_t)col * CQ + r] = l;
                        split1(v01, h, l); g_Qthi[base + (size_t)(col + 1) * CQ + r] = h; g_Qtlo[base + (size_t)(col + 1) * CQ + r] = l;
                        split1(v10, h, l); g_Qthi[base + (size_t)col * CQ + r + 8] = h;       g_Qtlo[base + (size_t)col * CQ + r + 8] = l;
                        split1(v11, h, l); g_Qthi[base + (size_t)(col + 1) * CQ + r + 8] = h; g_Qtlo[base + (size_t)(col + 1) * CQ + r + 8] = l;
                    } else {       // K -> split [o][n]
                        const int kr = r - 64;
                        const size_t base = (size_t)bz * CQ * NN;
                        __nv_bfloat162 h2, l2;
                        split_pack(v00, v01, h2, l2);
                        *(__nv_bfloat162*)&g_Khi[base + (size_t)kr * NN + col] = h2;
                        *(__nv_bfloat162*)&g_Klo[base + (size_t)kr * NN + col] = l2;
                        split_pack(v10, v11, h2, l2);
                        *(__nv_bfloat162*)&g_Khi[base + (size_t)(kr + 8) * NN + col] = h2;
                        *(__nv_bfloat162*)&g_Klo[base + (size_t)(kr + 8) * NN + col] = l2;
                    }
                } else {           // V rows (+bias) -> fp32 (single rounding happens in vrescale)
                    const int vr = r - 128;
                    float* dst = g_V + (size_t)bz * CC * NN;
                    const float b0 = bias[vr], b1 = bias[vr + 8];
                    *(float2*)&dst[(size_t)vr * NN + col]       = make_float2(v00 + b0, v01 + b0);
                    *(float2*)&dst[(size_t)(vr + 8) * NN + col] = make_float2(v10 + b1, v11 + b1);
                }
            }
    }

    if (EPI == 2) {
        float ssum[2][2] = {{0.f, 0.f}, {0.f, 0.f}};
        float ssq[2][2]  = {{0.f, 0.f}, {0.f, 0.f}};
#pragma unroll
        for (int mi = 0; mi < 2; mi++)
#pragma unroll
            for (int nj = 0; nj < 8; nj++) {
                const int r = row0 + wm * 32 + mi * 16 + gid;
                const int col = col0 + wn * 64 + nj * 8 + t4 * 2;
                const float b0 = bias[r], b1 = bias[r + 8];
                const float v00 = acc[mi][nj][0] + b0, v01 = acc[mi][nj][1] + b0;
                const float v10 = acc[mi][nj][2] + b1, v11 = acc[mi][nj][3] + b1;
                *(float2*)&C[(size_t)r * NN + col]       = make_float2(v00, v01);
                *(float2*)&C[(size_t)(r + 8) * NN + col] = make_float2(v10, v11);
                ssum[mi][0] += v00 + v01;  ssq[mi][0] += v00 * v00 + v01 * v01;
                ssum[mi][1] += v10 + v11;  ssq[mi][1] += v10 * v10 + v11 * v11;
            }
#pragma unroll
        for (int mi = 0; mi < 2; mi++)
#pragma unroll
            for (int h = 0; h < 2; h++) {
                const int r = row0 + wm * 32 + mi * 16 + gid + h * 8;
                atomicAdd(&g_sum[r], ssum[mi][h]);
                atomicAdd(&g_sumsq[r], ssq[mi][h]);
            }
    }

    if (EPI == 3) {
#pragma unroll
        for (int mi = 0; mi < 2; mi++)
#pragma unroll
            for (int nj = 0; nj < 8; nj++) {
                const int r = row0 + wm * 32 + mi * 16 + gid;
                const int col = col0 + wn * 64 + nj * 8 + t4 * 2;
                const float cs0 = 1.0f / (1e-9f + g_colsum[bz * NN + col]);
                const float cs1 = 1.0f / (1e-9f + g_colsum[bz * NN + col + 1]);
                const size_t base = (size_t)bz * CC * NN;
                const float d00 = aux[(size_t)r * NN + col]       - acc[mi][nj][0] * cs0;
                const float d01 = aux[(size_t)r * NN + col + 1]   - acc[mi][nj][1] * cs1;
                const float d10 = aux[(size_t)(r + 8) * NN + col]     - acc[mi][nj][2] * cs0;
                const float d11 = aux[(size_t)(r + 8) * NN + col + 1] - acc[mi][nj][3] * cs1;
                __nv_bfloat162 h2, l2;
                split_pack(d00, d01, h2, l2);
                *(__nv_bfloat162*)&g_dhi[base + (size_t)r * NN + col] = h2;
                *(__nv_bfloat162*)&g_dlo[base + (size_t)r * NN + col] = l2;
                split_pack(d10, d11, h2, l2);
                *(__nv_bfloat162*)&g_dhi[base + (size_t)(r + 8) * NN + col] = h2;
                *(__nv_bfloat162*)&g_dlo[base + (size_t)(r + 8) * NN + col] = l2;
            }
    }
}

// ---------------- fused energy + exp + rowsum -> U bf16 ----------------
// grid (8 colgroups, 32 row stripes, BB). Each CTA: 128 rows x 512 cols (4 tiles).
// Rowsum partials go to g_rspart[colgroup]; invrs_kernel reduces them.
#define QA_ST 72
#define KB_ST 136

__global__ __launch_bounds__(256)
void attn_kernel()
{
    extern __shared__ __align__(16) char dsm[];
    __nv_bfloat16* sQ = (__nv_bfloat16*)dsm;
    __nv_bfloat16* sK = sQ + 2 * 128 * QA_ST;
    float* s_rs = (float*)(sK + 2 * 2 * 64 * KB_ST);

    const int cg = blockIdx.x;          // column group: 4 tiles of 128 = 512 cols
    const int b  = blockIdx.z;
    const int r0 = blockIdx.y * 128;
    const int tid = threadIdx.x;
    const int lane = tid & 31, warp = tid >> 5;
    const int wm = warp & 3, wn = warp >> 2;

    if (tid < 128) s_rs[tid] = 0.f;

    const uint32_t sQb = (uint32_t)__cvta_generic_to_shared(sQ);
    const uint32_t sKb = (uint32_t)__cvta_generic_to_shared(sK);

    const __nv_bfloat16* Qhi = g_Qthi + (size_t)b * NN * CQ;
    const __nv_bfloat16* Qlo = g_Qtlo + (size_t)b * NN * CQ;
#pragma unroll
    for (int p = 0; p < 4; p++) {
        const int idx = p * 256 + tid;
        const int row = idx >> 3, c8 = (idx & 7) * 8;
        cpasync16(sQb + (uint32_t)(row * QA_ST + c8) * 2,
                  Qhi + (size_t)(r0 + row) * CQ + c8);
        cpasync16(sQb + (uint32_t)(128 * QA_ST + row * QA_ST + c8) * 2,
                  Qlo + (size_t)(r0 + row) * CQ + c8);
    }
    cp_commit();

    const __nv_bfloat16* Khi = g_Khi + (size_t)b * CQ * NN;
    const __nv_bfloat16* Klo = g_Klo + (size_t)b * CQ * NN;
    const int kr = tid >> 4, kc8 = (tid & 15) * 8;

    auto issueK = [&](int tile, int stage) {
        const int c0 = (cg * 4 + tile) * 128;
        const uint32_t base = sKb + (uint32_t)stage * (2 * 64 * KB_ST * 2);
#pragma unroll
        for (int c = 0; c < 4; c++) {
            const int r = kr + c * 16;
            cpasync16(base + (uint32_t)(r * KB_ST + kc8) * 2,
                      Khi + (size_t)r * NN + c0 + kc8);
            cpasync16(base + (uint32_t)(64 * KB_ST + r * KB_ST + kc8) * 2,
                      Klo + (size_t)r * NN + c0 + kc8);
        }
        cp_commit();
    };

    issueK(0, 0);

    const int lr = lane & 15, lc8 = (lane >> 4) * 8;
    const uint32_t aBase = sQb + (uint32_t)((wm * 32 + lr) * QA_ST + lc8) * 2;
    const uint32_t bBase = sKb + (uint32_t)(lr * KB_ST + wn * 64 + lc8) * 2;
    constexpr uint32_t QPLANE = 128 * QA_ST * 2;
    constexpr uint32_t KPLANE = 64 * KB_ST * 2;
    constexpr uint32_t KSTAGE = 2 * KPLANE;

    const int gid = lane >> 2, t4 = lane & 3;
    float rowsum[2][2] = {{0.f, 0.f}, {0.f, 0.f}};
    __nv_bfloat16* U = g_A + (size_t)b * NN * NN;

    for (int tile = 0; tile < 4; tile++) {
        const int cur = tile & 1;
        if (tile + 1 < 4) {
            issueK(tile + 1, cur ^ 1);
            asm volatile("cp.async.wait_group 1;" ::: "memory");
        } else {
            asm volatile("cp.async.wait_group 0;" ::: "memory");
        }
        __syncthreads();

        const uint32_t bS = cur * KSTAGE;

        float acc[2][8][4];
#pragma unroll
        for (int i = 0; i < 2; i++)
#pragma unroll
            for (int j = 0; j < 8; j++)
#pragma unroll
                for (int k = 0; k < 4; k++) acc[i][j][k] = 0.f;

#pragma unroll
        for (int ch = 0; ch < 4; ch++) {
            uint32_t ah[2][4], al[2][4];
#pragma unroll
            for (int mi = 0; mi < 2; mi++) {
                ldsm4(ah[mi], aBase + ch * 32 + mi * 16 * QA_ST * 2);
                ldsm4(al[mi], aBase + QPLANE + ch * 32 + mi * 16 * QA_ST * 2);
            }
            uint32_t bh[4][4], bl[4][4];
#pragma unroll
            for (int j = 0; j < 4; j++) {
                ldsm4t(bh[j], bBase + bS + ch * 16 * KB_ST * 2 + j * 16 * 2);
                ldsm4t(bl[j], bBase + bS + KPLANE + ch * 16 * KB_ST * 2 + j * 16 * 2);
            }
#pragma unroll
            for (int mi = 0; mi < 2; mi++)
#pragma unroll
                for (int j = 0; j < 4; j++) {
                    mma16816(acc[mi][2 * j],     ah[mi], &bh[j][0]);
                    mma16816(acc[mi][2 * j + 1], ah[mi], &bh[j][2]);
                    mma16816(acc[mi][2 * j],     ah[mi], &bl[j][0]);
                    mma16816(acc[mi][2 * j + 1], ah[mi], &bl[j][2]);
                    mma16816(acc[mi][2 * j],     al[mi], &bh[j][0]);
                    mma16816(acc[mi][2 * j + 1], al[mi], &bh[j][2]);
                }
        }

        const int c0 = (cg * 4 + tile) * 128;
#pragma unroll
        for (int mi = 0; mi < 2; mi++)
#pragma unroll
            for (int nj = 0; nj < 8; nj++) {
                const int row = r0 + wm * 32 + mi * 16 + gid;
                const int col = c0 + wn * 64 + nj * 8 + t4 * 2;
                const float e00 = __expf(acc[mi][nj][0]);
                const float e01 = __expf(acc[mi][nj][1]);
                const float e10 = __expf(acc[mi][nj][2]);
                const float e11 = __expf(acc[mi][nj][3]);
                rowsum[mi][0] += e00 + e01;
                rowsum[mi][1] += e10 + e11;
                __nv_bfloat162 p0, p1;
                p0.x = __float2bfloat16(e00); p0.y = __float2bfloat16(e01);
                p1.x = __float2bfloat16(e10); p1.y = __float2bfloat16(e11);
                *(__nv_bfloat162*)&U[(size_t)row * NN + col] = p0;
                *(__nv_bfloat162*)&U[(size_t)(row + 8) * NN + col] = p1;
            }
        __syncthreads();
    }

#pragma unroll
    for (int mi = 0; mi < 2; mi++)
#pragma unroll
        for (int h = 0; h < 2; h++) {
            float v = rowsum[mi][h];
            v += __shfl_xor_sync(0xffffffffu, v, 1);
            v += __shfl_xor_sync(0xffffffffu, v, 2);
            if (t4 == 0) atomicAdd(&s_rs[wm * 32 + mi * 16 + gid + h * 8], v);
        }
    __syncthreads();
    if (tid < 128) g_rspart[(size_t)cg * BB * NN + b * NN + r0 + tid] = s_rs[tid];
}

// ---------------- invrs: reduce 8 rowsum partials ----------------
__global__ void invrs_kernel()
{
    const int i = blockIdx.x * 256 + threadIdx.x;   // over BB*NN
    float s = 0.f;
#pragma unroll
    for (int p = 0; p < 8; p++) s += g_rspart[(size_t)p * BB * NN + i];
    g_invrs[i] = 1.0f / s;
}

// ---------------- V' = V_fp32 * invrs[n] -> single bf16 plane ----------------
__global__ void vrescale_kernel()
{
    const int b = blockIdx.z;
    const size_t i4 = (size_t)blockIdx.x * 256 + threadIdx.x;   // over CC*NN/4
    const float4 v = ((const float4*)(g_V + (size_t)b * CC * NN))[i4];
    const int n4 = (int)((i4 * 4) & (NN - 1));
    const float4 w = *(const float4*)&g_invrs[b * NN + n4];
    __nv_bfloat162 p0, p1;
    p0.x = __float2bfloat16(v.x * w.x); p0.y = __float2bfloat16(v.y * w.y);
    p1.x = __float2bfloat16(v.z * w.z); p1.y = __float2bfloat16(v.w * w.w);
    uint2 o;
    o.x = *(uint32_t*)&p0; o.y = *(uint32_t*)&p1;
    ((uint2*)(g_Vhi + (size_t)b * CC * NN))[i4] = o;
}

// ---------------- weighted column sums ----------------
__global__ void colsum_kernel()
{
    const int m2 = blockIdx.x * 256 + threadIdx.x;
    const int b = blockIdx.z;
    const int n0 = blockIdx.y * 128;
    const __nv_bfloat162* A2 = (const __nv_bfloat162*)(g_A + (size_t)b * NN * NN);
    float s0 = 0.f, s1 = 0.f;
#pragma unroll 4
    for (int n = 0; n < 128; n++) {
        const float w = g_invrs[b * NN + n0 + n];
        const __nv_bfloat162 a = A2[(size_t)(n0 + n) * (NN / 2) + m2];
        s0 += __bfloat162float(a.x) * w;
        s1 += __bfloat162float(a.y) * w;
    }
    atomicAdd(&g_colsum[b * NN + 2 * m2 + 0], s0);
    atomicAdd(&g_colsum[b * NN + 2 * m2 + 1], s1);
}

// ---------------- splits ----------------
__global__ void split4_kernel(const float* __restrict__ src, size_t srcBS,
                              __nv_bfloat16* __restrict__ hi, __nv_bfloat16* __restrict__ lo,
                              size_t dstBS)
{
    const size_t i4 = (size_t)blockIdx.x * 256 + threadIdx.x;
    const float4 v = ((const float4*)(src + (size_t)blockIdx.z * srcBS))[i4];
    __nv_bfloat162 ha, la, hb, lb;
    split_pack(v.x, v.y, ha, la);
    split_pack(v.z, v.w, hb, lb);
    uint2 hv, lv;
    hv.x = *(uint32_t*)&ha; hv.y = *(uint32_t*)&hb;
    lv.x = *(uint32_t*)&la; lv.y = *(uint32_t*)&lb;
    ((uint2*)(hi + (size_t)blockIdx.z * dstBS))[i4] = hv;
    ((uint2*)(lo + (size_t)blockIdx.z * dstBS))[i4] = lv;
}

__global__ void wqkv_split_kernel(const float* __restrict__ Wq, const float* __restrict__ Wk,
                                  const float* __restrict__ Wv)
{
    const int t = blockIdx.x * 256 + threadIdx.x;
    float v;
    if (t < 64 * CC) v = Wq[t];
    else if (t < 128 * CC) v = Wk[t - 64 * CC];
    else v = Wv[t - 128 * CC];
    __nv_bfloat16 h, l;
    split1(v, h, l);
    g_Wqkvhi[t] = h; g_Wqkvlo[t] = l;
}

// ---------------- misc ----------------
__global__ void zero_kernel()
{
    const int t = blockIdx.x * 256 + threadIdx.x;
    if (t < CC) { g_sum[t] = 0.f; g_sumsq[t] = 0.f; }
    if (t < BB * NN) g_colsum[t] = 0.f;
}

__global__ void bn_finalize_kernel(const float* __restrict__ gamma, const float* __restrict__ beta)
{
    const int c = threadIdx.x;
    const float cnt = (float)(BB * NN);
    const float mean = g_sum[c] / cnt;
    const float var = g_sumsq[c] / cnt - mean * mean;
    const float sc = gamma[c] * rsqrtf(var + 1e-5f);
    g_scale[c] = sc;
    g_shift[c] = beta[c] - mean * sc;
}

__global__ void final_kernel(const float* __restrict__ x, float* __restrict__ out)
{
    const size_t idx = (size_t)blockIdx.x * 256 + threadIdx.x;
    const int c = (int)((idx >> 12) & (CC - 1));
    const float t = g_T[idx] * g_scale[c] + g_shift[c];
    out[idx] = x[idx] + fmaxf(t, 0.f);
}

// ---------------- launch ----------------
extern "C" void kernel_launch(void* const* d_in, const int* in_sizes, int n_in,
                              void* d_out, int out_size)
{
    const float* x     = (const float*)d_in[0];
    const float* Wq    = (const float*)d_in[1];
    const float* Wk    = (const float*)d_in[2];
    const float* Wv    = (const float*)d_in[3];
    const float* bv    = (const float*)d_in[4];
    const float* Wt    = (const float*)d_in[5];
    const float* bt    = (const float*)d_in[6];
    const float* gamma = (const float*)d_in[7];
    const float* beta  = (const float*)d_in[8];
    float* out = (float*)d_out;

    float *pT;
    __nv_bfloat16 *pA, *pXhi, *pXlo, *pVhi, *pDhi, *pDlo;
    __nv_bfloat16 *pWqkvhi, *pWqkvlo, *pWthi, *pWtlo;
    cudaGetSymbolAddress((void**)&pT, g_T);
    cudaGetSymbolAddress((void**)&pA, g_A);
    cudaGetSymbolAddress((void**)&pXhi, g_xhi);
    cudaGetSymbolAddress((void**)&pXlo, g_xlo);
    cudaGetSymbolAddress((void**)&pVhi, g_Vhi);
    cudaGetSymbolAddress((void**)&pDhi, g_dhi);
    cudaGetSymbolAddress((void**)&pDlo, g_dlo);
    cudaGetSymbolAddress((void**)&pWqkvhi, g_Wqkvhi);
    cudaGetSymbolAddress((void**)&pWqkvlo, g_Wqkvlo);
    cudaGetSymbolAddress((void**)&pWthi, g_Wthi);
    cudaGetSymbolAddress((void**)&pWtlo, g_Wtlo);

    const int attn_smem = (2 * 128 * QA_ST + 2 * 2 * 64 * KB_ST) * 2 + 128 * 4;
    cudaFuncSetAttribute(attn_kernel, cudaFuncAttributeMaxDynamicSharedMemorySize, attn_smem);

    // mma gemm dynamic smem: 4 stages
    const int smem_22 = 4 * (2 * 128 * SA_STRIDE * 2 + 2 * 16 * SB_STRIDE * 2);  // 83968
    const int smem_11 = 4 * (1 * 128 * SA_STRIDE * 2 + 1 * 16 * SB_STRIDE * 2);  // 41984
    cudaFuncSetAttribute(mma_gemm_kernel<2, 2, 1>, cudaFuncAttributeMaxDynamicSharedMemorySize, smem_22);
    cudaFuncSetAttribute(mma_gemm_kernel<2, 2, 2>, cudaFuncAttributeMaxDynamicSharedMemorySize, smem_22);
    cudaFuncSetAttribute(mma_gemm_kernel<1, 1, 3>, cudaFuncAttributeMaxDynamicSharedMemorySize, smem_11);

    zero_kernel<<<BB * NN / 256, 256>>>();
    wqkv_split_kernel<<<384 * CC / 256, 256>>>(Wq, Wk, Wv);
    split4_kernel<<<dim3(CC * CC / 1024, 1, 1), 256>>>(Wt, 0, pWthi, pWtlo, 0);
    split4_kernel<<<dim3(CC * NN / 1024, 1, BB), 256>>>(x, (size_t)CC * NN, pXhi, pXlo, (size_t)CC * NN);

    // stacked QKV projection: [384,256] @ [256,4096]; epilogue writes Qt/K splits + V fp32
    mma_gemm_kernel<2, 2, 1><<<dim3(NN / 128, 3, BB), 256, smem_22>>>(
        pWqkvhi, pWqkvlo, CC, 0,
        pXhi, pXlo, (size_t)CC * NN,
        pT /*unused*/, 0, CC, bv, nullptr, 0);

    // fused energy + exp + rowsum -> U (bf16), rowsum partials (column-split grid)
    attn_kernel<<<dim3(8, NN / 128, BB), 256, attn_smem>>>();

    // invrs = 1 / sum of 8 partials
    invrs_kernel<<<BB * NN / 256, 256>>>();

    // V' = V_fp32 * invrs[n] -> single bf16 plane
    vrescale_kernel<<<dim3(CC * NN / 1024, 1, BB), 256>>>();

    // weighted column sums for L1 renorm
    colsum_kernel<<<dim3(NN / 512, NN / 128, BB), 256>>>();

    // x_r = V' @ U (single-product); epilogue computes d = x - xr*colscale, writes d splits
    mma_gemm_kernel<1, 1, 3><<<dim3(NN / 128, CC / 128, BB), 256, smem_11>>>(
        pVhi, nullptr, NN, (size_t)CC * NN,
        pA, nullptr, (size_t)NN * NN,
        pT /*unused*/, 0, NN, nullptr, x, (size_t)CC * NN);

    // t = Wt @ d + bt, with BN stats -> g_T
    mma_gemm_kernel<2, 2, 2><<<dim3(NN / 128, CC / 128, BB), 256, smem_22>>>(
        pWthi, pWtlo, CC, 0,
        pDhi, pDlo, (size_t)CC * NN,
        pT, (size_t)CC * NN, CC, bt, nullptr, 0);

    bn_finalize_kernel<<<1, CC>>>(gamma, beta);

    final_kernel<<<(size_t)BB * CC * NN / 256, 256>>>(x, out);
}